// round 1
// baseline (speedup 1.0000x reference)
#include <cuda_runtime.h>
#include <math.h>

#define NP 4096
#define PI_F     3.1415927410125732f
#define TWOPI_F  6.2831854820251465f
#define HALFPI_F 1.5707963705062866f

// scratch (no allocation allowed)
static __device__ float g_ang[NP];
static __device__ float g_bx[2][NP];
static __device__ float g_by[2][NP];
static __device__ float g_cms[2];

__device__ __forceinline__ float wrapf(float d) {
    // replicates: where(d <= -pi, jnp.mod(d, pi), d); then d -= (d >= pi) * 2pi
    if (d <= -PI_F) {
        float r = fmodf(d, PI_F);        // C-style remainder
        if (r < 0.f) r += PI_F;          // python-mod sign fix (divisor pi > 0)
        d = r;
    }
    if (d >= PI_F) d -= TWOPI_F;
    return d;
}

// ---------------------------------------------------------------------------
// prep: per-particle angle + deterministic global position sum (cms)
// ---------------------------------------------------------------------------
__global__ void prep_kernel(const float* __restrict__ pre, const float* __restrict__ pim,
                            const float* __restrict__ ore, const float* __restrict__ oim) {
    __shared__ float sx[1024], sy[1024];
    int t = threadIdx.x;
    float ax = 0.f, ay = 0.f;
    for (int i = t; i < NP; i += 1024) {
        g_ang[i] = atan2f(oim[i], ore[i]);
        ax += pre[i];
        ay += pim[i];
    }
    sx[t] = ax; sy[t] = ay;
    __syncthreads();
    for (int s = 512; s > 0; s >>= 1) {
        if (t < s) { sx[t] += sx[t + s]; sy[t] += sy[t + s]; }
        __syncthreads();
    }
    if (t == 0) {
        g_cms[0] = sx[0] * (1.0f / NP);   // n_a = 4096 exactly, /4096 exact scale
        g_cms[1] = sy[0] * (1.0f / NP);
    }
}

// ---------------------------------------------------------------------------
// pairwise forces + per-particle epilogue
// 128 blocks x 256 threads. tid = js*32 + ii ; i = blk*32+ii ; j strided by 8.
// Lanes of a warp share js -> shared loads of j-data are broadcasts.
// ---------------------------------------------------------------------------
__global__ void pair_kernel(const float* __restrict__ pre, const float* __restrict__ pim,
                            const float* __restrict__ ore, const float* __restrict__ oim,
                            const float* __restrict__ deltas, const float* __restrict__ rnoise,
                            const float* __restrict__ tnre, const float* __restrict__ tnim,
                            float* __restrict__ out) {
    extern __shared__ float sh[];
    float* s_px = sh;
    float* s_py = sh + NP;
    float* s_ag = sh + 2 * NP;
    float* s_or = sh + 3 * NP;
    float* s_oi = sh + 4 * NP;
    float* s_rd = sh + 5 * NP;   // 5 * 8 * 32 floats

    int tid = threadIdx.x;
    for (int k = tid; k < NP; k += 256) {
        s_px[k] = pre[k];
        s_py[k] = pim[k];
        s_ag[k] = g_ang[k];
        s_or[k] = ore[k];
        s_oi[k] = oim[k];
    }
    __syncthreads();

    int ii = tid & 31, js = tid >> 5;
    int i = blockIdx.x * 32 + ii;

    float pxi = s_px[i], pyi = s_py[i], agi = s_ag[i];

    const float ROCf  = (float)(2.5e-5 + 3.15e-6);     // RO + RC
    const float ROC2G = ROCf * ROCf * 1.0005f;         // squared prefilter w/ guard
    const float RRf   = (float)(8e-6);

    float nr = 0.f, sxv = 0.f, syv = 0.f, oxv = 0.f, oyv = 0.f;

    for (int j = js; j < NP; j += 8) {
        float pxj = s_px[j], pyj = s_py[j];
        float dx = pxi - pxj, dy = pyi - pyj;
        float r2 = fmaf(dx, dx, dy * dy);
        bool same = (j == i);
        if (r2 <= ROC2G || same) {
            float dist = same ? 1.0f : __fsqrt_rn(r2);  // diag dist = 1 (eye)
            if (dist <= ROCf || same) {                 // mask_ro (self included)
                oxv += s_or[j];
                oyv += s_oi[j];
            }
            if (dist <= RRf && !same) {                 // mask_rr (self excluded)
                float ad = agi - s_ag[j];
                if (ad <= -PI_F) { float r = fmodf(ad, PI_F); if (r < 0.f) r += PI_F; ad = r; }
                if (ad >= PI_F) ad -= TWOPI_F;
                if (fabsf(ad) < HALFPI_F) {             // in_front
                    nr += 1.0f; sxv += pxj; syv += pyj;
                }
            }
        }
    }

    // partial reduction across the 8 j-slots
    float* Rnr = s_rd;
    float* Rsx = s_rd + 256;
    float* Rsy = s_rd + 512;
    float* Rox = s_rd + 768;
    float* Roy = s_rd + 1024;
    Rnr[js * 32 + ii] = nr;
    Rsx[js * 32 + ii] = sxv;
    Rsy[js * 32 + ii] = syv;
    Rox[js * 32 + ii] = oxv;
    Roy[js * 32 + ii] = oyv;
    __syncthreads();

    if (tid < 32) {
        int ip = blockIdx.x * 32 + tid;
        float Nr = 0.f, Sx = 0.f, Sy = 0.f, Ox = 0.f, Oy = 0.f;
        #pragma unroll
        for (int k = 0; k < 8; k++) {
            Nr += Rnr[k * 32 + tid];
            Sx += Rsx[k * 32 + tid];
            Sy += Rsy[k * 32 + tid];
            Ox += Rox[k * 32 + tid];
            Oy += Roy[k * 32 + tid];
        }
        float px = s_px[ip], py = s_py[ip];
        float orr = s_or[ip], ori = s_oi[ip];

        // repulsion vector d = -S
        float sgn = (Nr > 0.f) ? 1.f : 0.f;
        float den = fmaxf(Nr, 1.f);
        float SSx = Sx / den - px * sgn;
        float SSy = Sy / den - py * sgn;
        float ddx = -SSx, ddy = -SSy;

        // Ps = cms - pos (Ra = inf)
        float Px = g_cms[0] - px;
        float Py = g_cms[1] - py;

        float del = deltas[ip];
        float cd = cosf(del), sd = sinf(del);
        float lx = Px * cd - Py * sd;   // Ps * e^{+i delta}
        float ly = Px * sd + Py * cd;
        float rxx = Px * cd + Py * sd;  // Ps * e^{-i delta}
        float ryy = Py * cd - Px * sd;

        // cossim with eps clamps (faithful to reference)
        float dl = lx * Ox + ly * Oy;
        float dr = rxx * Ox + ryy * Oy;
        float no = fmaxf(__fsqrt_rn(Ox * Ox + Oy * Oy), 1e-14f);
        float cl = dl / (fmaxf(__fsqrt_rn(lx * lx + ly * ly), 1e-14f) * no);
        float cr = dr / (fmaxf(__fsqrt_rn(rxx * rxx + ryy * ryy), 1e-14f) * no);
        bool usel = (cl >= cr);
        float bx = usel ? lx : rxx;
        float by = usel ? ly : ryy;

        bool hasrep = (ddx != 0.f) || (ddy != 0.f);
        float tx = hasrep ? ddx : bx;
        float ty = hasrep ? ddy : by;
        float att = wrapf(atan2f(ty, tx) - atan2f(ori, orr));

        const float CTH  = (float)(0.2 * 25.0 * 0.0028);        // DT*GAMMA*DR
        const float S2DR = (float)0.07483314773547883;           // sqrt(2*DR)
        const float SDT  = (float)0.4472135954999579;            // sqrt(DT)
        float theta = CTH * sinf(att) + rnoise[ip] * S2DR * SDT;
        float rc = cosf(theta), rs = sinf(theta);
        float nore = orr * rc - ori * rs;
        float noim = orr * rs + ori * rc;

        const float CH   = (float)0.7071067811865476;            // sqrt(0.5)
        const float CTT  = (float)1.6733200530681511e-7;         // sqrt(2*DT_TRANS)
        const float DTVEL = (float)(0.2 * 5e-7);                 // DT*VEL
        float tnr = tnre[ip] * CH * CTT;
        float tni = tnim[ip] * CH * CTT;
        float p0x = px + (DTVEL * orr + tnr * SDT);
        float p0y = py + (DTVEL * ori + tni * SDT);
        g_bx[0][ip] = p0x;
        g_by[0][ip] = p0y;

        // outputs k=1..4 (k=0 positions written by final collision sweep)
        out[(1 * NP + ip) * 2 + 0] = nore;
        out[(1 * NP + ip) * 2 + 1] = noim;
        out[(2 * NP + ip) * 2 + 0] = Ox;
        out[(2 * NP + ip) * 2 + 1] = Oy;
        out[(3 * NP + ip) * 2 + 0] = lx;
        out[(3 * NP + ip) * 2 + 1] = ly;
        out[(4 * NP + ip) * 2 + 0] = rxx;
        out[(4 * NP + ip) * 2 + 1] = ryy;
    }
}

// ---------------------------------------------------------------------------
// one collision-resolution sweep: p_i -= sum_j [coll] (p_j-p_i)/|..|*(2.1Rc-|..|)/2
// ping-pong buffers selected by src; final sweep writes d_out positions.
// ---------------------------------------------------------------------------
__global__ void collide_kernel(int src, float* __restrict__ outpos) {
    __shared__ float s_px[NP], s_py[NP];
    __shared__ float Rx[8][32], Ry[8][32];
    int tid = threadIdx.x;
    const float* inx = g_bx[src];
    const float* iny = g_by[src];
    for (int k = tid; k < NP; k += 256) {
        s_px[k] = inx[k];
        s_py[k] = iny[k];
    }
    __syncthreads();

    int ii = tid & 31, js = tid >> 5;
    int i = blockIdx.x * 32 + ii;
    float pxi = s_px[i], pyi = s_py[i];

    const float THR   = (float)(2.0 * 3.15e-6);     // 2*Rc
    const float THR2G = THR * THR * 1.0005f;
    const float MOVC  = (float)(2.1 * 3.15e-6);

    float mx = 0.f, my = 0.f;
    for (int j = js; j < NP; j += 8) {
        float dx = s_px[j] - pxi;          // p_j - p_i
        float dy = s_py[j] - pyi;
        float r2 = fmaf(dx, dx, dy * dy);
        if (r2 <= THR2G && j != i) {
            float absd = __fsqrt_rn(r2);
            if (absd <= THR) {
                float f = (MOVC - absd) * 0.5f;
                mx += (dx / absd) * f;
                my += (dy / absd) * f;
            }
        }
    }
    Rx[js][ii] = mx;
    Ry[js][ii] = my;
    __syncthreads();

    if (tid < 32) {
        int ip = blockIdx.x * 32 + tid;
        float ax = 0.f, ay = 0.f;
        #pragma unroll
        for (int k = 0; k < 8; k++) { ax += Rx[k][tid]; ay += Ry[k][tid]; }
        float nx = s_px[ip] - ax;
        float ny = s_py[ip] - ay;
        g_bx[src ^ 1][ip] = nx;
        g_by[src ^ 1][ip] = ny;
        if (outpos) {
            outpos[ip * 2 + 0] = nx;
            outpos[ip * 2 + 1] = ny;
        }
    }
}

// ---------------------------------------------------------------------------
extern "C" void kernel_launch(void* const* d_in, const int* in_sizes, int n_in,
                              void* d_out, int out_size) {
    const float* pre    = (const float*)d_in[0];
    const float* pim    = (const float*)d_in[1];
    const float* ore    = (const float*)d_in[2];
    const float* oim    = (const float*)d_in[3];
    const float* deltas = (const float*)d_in[4];
    const float* rnoise = (const float*)d_in[5];
    const float* tnre   = (const float*)d_in[6];
    const float* tnim   = (const float*)d_in[7];
    float* out = (float*)d_out;

    prep_kernel<<<1, 1024>>>(pre, pim, ore, oim);

    const int PAIR_SMEM = (5 * NP + 5 * 256) * (int)sizeof(float);  // 87040 B
    cudaFuncSetAttribute(pair_kernel, cudaFuncAttributeMaxDynamicSharedMemorySize, PAIR_SMEM);
    pair_kernel<<<NP / 32, 256, PAIR_SMEM>>>(pre, pim, ore, oim, deltas, rnoise, tnre, tnim, out);

    for (int t = 0; t < 30; t++) {
        collide_kernel<<<NP / 32, 256>>>(t & 1, (t == 29) ? out : (float*)nullptr);
    }
}

// round 4
// speedup vs baseline: 1.8299x; 1.8299x over previous
#include <cuda_runtime.h>
#include <math.h>

#define NP 4096
#define PI_F     3.1415927410125732f
#define TWOPI_F  6.2831854820251465f
#define HALFPI_F 1.5707963705062866f

// scratch (no allocation allowed)
static __device__ float  g_ang[NP];
static __device__ float2 g_pos[NP];                     // pos + trans (pre-collision)
static __device__ unsigned short g_nbr[8 * 16 * NP];    // [slot][k][i] transposed, coalesced
static __device__ unsigned char  g_cnt[NP * 8];         // [i][slot]
static __device__ float g_cms[2];

__device__ __forceinline__ float wrapf(float d) {
    // replicates: where(d <= -pi, jnp.mod(d, pi), d); then d -= (d >= pi) * 2pi
    if (d <= -PI_F) {
        float r = fmodf(d, PI_F);
        if (r < 0.f) r += PI_F;          // python-mod sign fix
        d = r;
    }
    if (d >= PI_F) d -= TWOPI_F;
    return d;
}

// ---------------------------------------------------------------------------
// prep: per-particle angle + deterministic global position sum (cms)
// ---------------------------------------------------------------------------
__global__ void __launch_bounds__(1024, 1)
prep_kernel(const float* __restrict__ pre, const float* __restrict__ pim,
            const float* __restrict__ ore, const float* __restrict__ oim) {
    __shared__ float sx[1024], sy[1024];
    int t = threadIdx.x;
    float ax = 0.f, ay = 0.f;
    for (int i = t; i < NP; i += 1024) {
        g_ang[i] = atan2f(oim[i], ore[i]);
        ax += pre[i];
        ay += pim[i];
    }
    sx[t] = ax; sy[t] = ay;
    __syncthreads();
    for (int s = 512; s > 0; s >>= 1) {
        if (t < s) { sx[t] += sx[t + s]; sy[t] += sy[t + s]; }
        __syncthreads();
    }
    if (t == 0) {
        g_cms[0] = sx[0] * (1.0f / NP);   // n_a = 4096 exactly
        g_cms[1] = sy[0] * (1.0f / NP);
    }
}

// ---------------------------------------------------------------------------
// pairwise forces + per-particle epilogue + collision candidate-list build
// 128 blocks x 256 threads. tid = js*32 + ii ; i = blk*32+ii ; j strided by 8.
// ---------------------------------------------------------------------------
__global__ void __launch_bounds__(256)
pair_kernel(const float* __restrict__ pre, const float* __restrict__ pim,
            const float* __restrict__ ore, const float* __restrict__ oim,
            const float* __restrict__ deltas, const float* __restrict__ rnoise,
            const float* __restrict__ tnre, const float* __restrict__ tnim,
            float* __restrict__ out) {
    extern __shared__ float sh[];
    float2* s_p  = (float2*)sh;            // NP float2
    float2* s_o  = (float2*)(sh + 2 * NP); // NP float2
    float*  s_ag = sh + 4 * NP;            // NP
    float*  s_rd = sh + 5 * NP;            // 5 * 256

    int tid = threadIdx.x;
    for (int k = tid; k < NP; k += 256) {
        s_p[k]  = make_float2(pre[k], pim[k]);
        s_o[k]  = make_float2(ore[k], oim[k]);
        s_ag[k] = g_ang[k];
    }
    __syncthreads();

    int ii = tid & 31, js = tid >> 5;
    int i = blockIdx.x * 32 + ii;

    float pxi = s_p[i].x, pyi = s_p[i].y, agi = s_ag[i];

    const float ROCf  = (float)(2.5e-5 + 3.15e-6);      // RO + RC
    const float ROC2G = ROCf * ROCf * 1.0005f;          // squared prefilter w/ guard
    const float RRf   = (float)(8e-6);
    const float RCAP  = (float)(12.0 * 3.15e-6);        // collision capture radius
    const float RCAP2 = RCAP * RCAP;

    float nr = 0.f, sxv = 0.f, syv = 0.f, oxv = 0.f, oyv = 0.f;
    int c = 0;

    for (int j = js; j < NP; j += 8) {
        float2 pj = s_p[j];
        float dx = pxi - pj.x, dy = pyi - pj.y;
        float r2 = fmaf(dx, dx, dy * dy);
        bool same = (j == i);
        if (r2 <= RCAP2 || same) {
            if (!same) {                                 // collision candidate
                if (c < 16) g_nbr[(js * 16 + c) * NP + i] = (unsigned short)j;
                c++;
            }
            if (r2 <= ROC2G || same) {
                float dist = same ? 1.0f : __fsqrt_rn(r2);
                if (dist <= ROCf || same) {              // mask_ro (self included)
                    oxv += s_o[j].x;
                    oyv += s_o[j].y;
                }
                if (dist <= RRf && !same) {              // mask_rr (self excluded)
                    float ad = agi - s_ag[j];
                    if (ad <= -PI_F) { float r = fmodf(ad, PI_F); if (r < 0.f) r += PI_F; ad = r; }
                    if (ad >= PI_F) ad -= TWOPI_F;
                    if (fabsf(ad) < HALFPI_F) {          // in_front
                        nr += 1.0f; sxv += pj.x; syv += pj.y;
                    }
                }
            }
        }
    }
    g_cnt[i * 8 + js] = (unsigned char)(c > 16 ? 16 : c);

    // partial reduction across the 8 j-slots
    float* Rnr = s_rd;
    float* Rsx = s_rd + 256;
    float* Rsy = s_rd + 512;
    float* Rox = s_rd + 768;
    float* Roy = s_rd + 1024;
    Rnr[js * 32 + ii] = nr;
    Rsx[js * 32 + ii] = sxv;
    Rsy[js * 32 + ii] = syv;
    Rox[js * 32 + ii] = oxv;
    Roy[js * 32 + ii] = oyv;
    __syncthreads();

    if (tid < 32) {
        int ip = blockIdx.x * 32 + tid;
        float Nr = 0.f, Sx = 0.f, Sy = 0.f, Ox = 0.f, Oy = 0.f;
        #pragma unroll
        for (int k = 0; k < 8; k++) {
            Nr += Rnr[k * 32 + tid];
            Sx += Rsx[k * 32 + tid];
            Sy += Rsy[k * 32 + tid];
            Ox += Rox[k * 32 + tid];
            Oy += Roy[k * 32 + tid];
        }
        float px = s_p[ip].x, py = s_p[ip].y;
        float orr = s_o[ip].x, ori = s_o[ip].y;

        // repulsion vector d = -S
        float sgn = (Nr > 0.f) ? 1.f : 0.f;
        float den = fmaxf(Nr, 1.f);
        float SSx = Sx / den - px * sgn;
        float SSy = Sy / den - py * sgn;
        float ddx = -SSx, ddy = -SSy;

        // Ps = cms - pos (Ra = inf)
        float Px = g_cms[0] - px;
        float Py = g_cms[1] - py;

        float del = deltas[ip];
        float cd = cosf(del), sd = sinf(del);
        float lx = Px * cd - Py * sd;   // Ps * e^{+i delta}
        float ly = Px * sd + Py * cd;
        float rxx = Px * cd + Py * sd;  // Ps * e^{-i delta}
        float ryy = Py * cd - Px * sd;

        float dl = lx * Ox + ly * Oy;
        float dr = rxx * Ox + ryy * Oy;
        float no = fmaxf(__fsqrt_rn(Ox * Ox + Oy * Oy), 1e-14f);
        float cl = dl / (fmaxf(__fsqrt_rn(lx * lx + ly * ly), 1e-14f) * no);
        float cr = dr / (fmaxf(__fsqrt_rn(rxx * rxx + ryy * ryy), 1e-14f) * no);
        bool usel = (cl >= cr);
        float bx = usel ? lx : rxx;
        float by = usel ? ly : ryy;

        bool hasrep = (ddx != 0.f) || (ddy != 0.f);
        float tx = hasrep ? ddx : bx;
        float ty = hasrep ? ddy : by;
        float att = wrapf(atan2f(ty, tx) - atan2f(ori, orr));

        const float CTH  = (float)(0.2 * 25.0 * 0.0028);         // DT*GAMMA*DR
        const float S2DR = (float)0.07483314773547883;           // sqrt(2*DR)
        const float SDT  = (float)0.4472135954999579;            // sqrt(DT)
        float theta = CTH * sinf(att) + rnoise[ip] * S2DR * SDT;
        float rc = cosf(theta), rs = sinf(theta);
        float nore = orr * rc - ori * rs;
        float noim = orr * rs + ori * rc;

        const float CH    = (float)0.7071067811865476;           // sqrt(0.5)
        const float CTT   = (float)1.6733200530681511e-7;        // sqrt(2*DT_TRANS)
        const float DTVEL = (float)(0.2 * 5e-7);                 // DT*VEL
        float tnr = tnre[ip] * CH * CTT;
        float tni = tnim[ip] * CH * CTT;
        g_pos[ip] = make_float2(px + (DTVEL * orr + tnr * SDT),
                                py + (DTVEL * ori + tni * SDT));

        out[(1 * NP + ip) * 2 + 0] = nore;
        out[(1 * NP + ip) * 2 + 1] = noim;
        out[(2 * NP + ip) * 2 + 0] = Ox;
        out[(2 * NP + ip) * 2 + 1] = Oy;
        out[(3 * NP + ip) * 2 + 0] = lx;
        out[(3 * NP + ip) * 2 + 1] = ly;
        out[(4 * NP + ip) * 2 + 0] = rxx;
        out[(4 * NP + ip) * 2 + 1] = ryy;
    }
}

// ---------------------------------------------------------------------------
// fused collision sweeps: ONE block, smem ping-pong, neighbor-list only,
// early break when a sweep finds zero collisions (matches reference `cont`).
// ---------------------------------------------------------------------------
__global__ void __launch_bounds__(1024, 1)
sweep_kernel(float* __restrict__ outpos) {
    extern __shared__ float2 P[];
    float2* P0 = P;
    float2* P1 = P + NP;
    __shared__ int s_any;
    int tid = threadIdx.x;

    for (int k = tid; k < NP; k += 1024) P0[k] = g_pos[k];
    unsigned char counts[4][8];
    #pragma unroll
    for (int s = 0; s < 4; s++) {
        unsigned long long cc = *(const unsigned long long*)&g_cnt[(tid + s * 1024) * 8];
        #pragma unroll
        for (int slot = 0; slot < 8; slot++)
            counts[s][slot] = (unsigned char)((cc >> (slot * 8)) & 0xFF);
    }
    if (tid == 0) s_any = 0;
    __syncthreads();

    const float THR   = (float)(2.0 * 3.15e-6);     // 2*Rc
    const float THR2G = THR * THR * 1.0005f;
    const float MOVC  = (float)(2.1 * 3.15e-6);

    float2* finalP = P0;
    for (int t = 0; t < 30; t++) {
        float2* C  = (t & 1) ? P1 : P0;
        float2* Nx = (t & 1) ? P0 : P1;
        int mycoll = 0;
        #pragma unroll
        for (int s = 0; s < 4; s++) {
            int i = tid + s * 1024;
            float2 p = C[i];
            float mx = 0.f, my = 0.f;
            #pragma unroll
            for (int slot = 0; slot < 8; slot++) {
                int cnt = counts[s][slot];
                for (int k = 0; k < cnt; k++) {
                    int j = g_nbr[(slot * 16 + k) * NP + i];
                    float2 q = C[j];
                    float dx = q.x - p.x, dy = q.y - p.y;   // p_j - p_i
                    float r2 = fmaf(dx, dx, dy * dy);
                    if (r2 <= THR2G) {
                        float absd = __fsqrt_rn(r2);
                        if (absd <= THR) {
                            float f = (MOVC - absd) * 0.5f;
                            mx += (dx / absd) * f;
                            my += (dy / absd) * f;
                            mycoll = 1;
                        }
                    }
                }
            }
            Nx[i] = make_float2(p.x - mx, p.y - my);
        }
        if (mycoll) atomicOr(&s_any, 1);
        __syncthreads();                 // Nx + s_any visible
        finalP = Nx;
        int any = s_any;
        if (!any) break;                 // uniform: no collisions -> frozen forever
        __syncthreads();                 // all read s_any before reset
        if (tid == 0) s_any = 0;
        __syncthreads();                 // reset visible before next atomicOr
    }

    for (int k = tid; k < NP; k += 1024)
        ((float2*)outpos)[k] = finalP[k];
}

// ---------------------------------------------------------------------------
extern "C" void kernel_launch(void* const* d_in, const int* in_sizes, int n_in,
                              void* d_out, int out_size) {
    const float* pre    = (const float*)d_in[0];
    const float* pim    = (const float*)d_in[1];
    const float* ore    = (const float*)d_in[2];
    const float* oim    = (const float*)d_in[3];
    const float* deltas = (const float*)d_in[4];
    const float* rnoise = (const float*)d_in[5];
    const float* tnre   = (const float*)d_in[6];
    const float* tnim   = (const float*)d_in[7];
    float* out = (float*)d_out;

    prep_kernel<<<1, 1024>>>(pre, pim, ore, oim);

    const int PAIR_SMEM = (5 * NP + 5 * 256) * (int)sizeof(float);  // 87040 B
    cudaFuncSetAttribute(pair_kernel, cudaFuncAttributeMaxDynamicSharedMemorySize, PAIR_SMEM);
    pair_kernel<<<NP / 32, 256, PAIR_SMEM>>>(pre, pim, ore, oim, deltas, rnoise, tnre, tnim, out);

    const int SWEEP_SMEM = 2 * NP * (int)sizeof(float2);            // 65536 B
    cudaFuncSetAttribute(sweep_kernel, cudaFuncAttributeMaxDynamicSharedMemorySize, SWEEP_SMEM);
    sweep_kernel<<<1, 1024, SWEEP_SMEM>>>(out);
}

// round 5
// speedup vs baseline: 5.7115x; 3.1212x over previous
#include <cuda_runtime.h>
#include <math.h>

#define NP    4096
#define NSLOT 16
#define CAPS  6        // per-slot candidate cap (global list)
#define CAPT  12       // per-particle total cap (smem list)
#define NBLK  128
#define NTHR  512

#define PI_F     3.1415927410125732f
#define TWOPI_F  6.2831854820251465f
#define HALFPI_F 1.5707963705062866f

// scratch (no allocation allowed)
static __device__ float2 g_pos[NP];                       // pos + trans (pre-collision)
static __device__ unsigned short g_nbr[NSLOT * CAPS * NP]; // [slot][k][i]
static __device__ unsigned char  g_cnt[NP * NSLOT];        // [i][slot]
static __device__ int g_done;                              // zero-init; reset by sweep block

__device__ __forceinline__ float wrapf(float d) {
    // replicates: where(d <= -pi, jnp.mod(d, pi), d); then d -= (d >= pi) * 2pi
    if (d <= -PI_F) {
        float r = fmodf(d, PI_F);
        if (r < 0.f) r += PI_F;          // python-mod sign fix
        d = r;
    }
    if (d >= PI_F) d -= TWOPI_F;
    return d;
}

// smem union:
//  pair view : s_p[NP] float2 | s_o[NP] float2 | s_ag[NP] f32 | s_red[5*512] f32
//  sweep view: s_pos[NP] float2 | s_nbr[CAPT*NP] u16 | s_cnt[NP] u8
#define SMEM_BYTES (32768 + 98304 + 4096)   // sweep view = 135168 > pair view 92160

__global__ void __launch_bounds__(NTHR, 1)
fused_kernel(const float* __restrict__ pre, const float* __restrict__ pim,
             const float* __restrict__ ore, const float* __restrict__ oim,
             const float* __restrict__ deltas, const float* __restrict__ rnoise,
             const float* __restrict__ tnre, const float* __restrict__ tnim,
             float* __restrict__ out) {
    extern __shared__ char smem[];
    float2* s_p  = (float2*)smem;                    // 32768
    float2* s_o  = (float2*)(smem + 32768);          // 32768
    float*  s_ag = (float*)(smem + 65536);           // 16384
    float*  s_red = (float*)(smem + 81920);          // 10240

    __shared__ float s_cms[2];
    __shared__ int s_last, s_any;

    int tid = threadIdx.x;

    // ---- phase A: load + angles + cms (per-block, deterministic order) ----
    float ax = 0.f, ay = 0.f;
    for (int k = tid; k < NP; k += NTHR) {
        float px = pre[k], py = pim[k];
        s_p[k] = make_float2(px, py);
        float oxr = ore[k], oyi = oim[k];
        s_o[k] = make_float2(oxr, oyi);
        s_ag[k] = atan2f(oyi, oxr);
        ax += px; ay += py;
    }
    s_red[tid] = ax; s_red[512 + tid] = ay;
    __syncthreads();
    for (int s = 256; s > 0; s >>= 1) {
        if (tid < s) { s_red[tid] += s_red[tid + s]; s_red[512 + tid] += s_red[512 + tid + s]; }
        __syncthreads();
    }
    if (tid == 0) {
        s_cms[0] = s_red[0] * (1.0f / NP);     // n_a = 4096 exactly
        s_cms[1] = s_red[512] * (1.0f / NP);
    }
    __syncthreads();

    // ---- phase B: pairwise scan.  16 j-slots x 32 i-lanes ----
    int ii = tid & 31, js = tid >> 5;
    int i = blockIdx.x * 32 + ii;
    float pxi = s_p[i].x, pyi = s_p[i].y, agi = s_ag[i];

    const float ROCf  = (float)(2.5e-5 + 3.15e-6);   // RO + RC = 28.15um
    const float ROC2G = ROCf * ROCf * 1.0005f;       // squared prefilter w/ guard
    const float RRf   = (float)(8e-6);
    const float RCAP  = (float)(6.0 * 3.15e-6);      // collision capture radius 6*Rc
    const float RCAP2 = RCAP * RCAP;

    float nr = 0.f, sxv = 0.f, syv = 0.f, oxv = 0.f, oyv = 0.f;
    int c = 0;

    for (int j = js; j < NP; j += NSLOT) {
        float2 pj = s_p[j];
        float dx = pxi - pj.x, dy = pyi - pj.y;
        float r2 = fmaf(dx, dx, dy * dy);
        bool same = (j == i);
        if (r2 <= ROC2G || same) {
            if (r2 <= RCAP2 && !same) {                 // collision candidate
                if (c < CAPS) g_nbr[(js * CAPS + c) * NP + i] = (unsigned short)j;
                c++;
            }
            float dist = same ? 1.0f : __fsqrt_rn(r2);  // diag dist = 1 (eye)
            if (dist <= ROCf || same) {                 // mask_ro (self included)
                oxv += s_o[j].x;
                oyv += s_o[j].y;
            }
            if (dist <= RRf && !same) {                 // mask_rr (self excluded)
                float ad = agi - s_ag[j];
                if (ad <= -PI_F) { float r = fmodf(ad, PI_F); if (r < 0.f) r += PI_F; ad = r; }
                if (ad >= PI_F) ad -= TWOPI_F;
                if (fabsf(ad) < HALFPI_F) {             // in_front
                    nr += 1.0f; sxv += pj.x; syv += pj.y;
                }
            }
        }
    }
    g_cnt[i * NSLOT + js] = (unsigned char)(c > CAPS ? CAPS : c);

    // partial reduction across the 16 j-slots
    float* Rnr = s_red;
    float* Rsx = s_red + 512;
    float* Rsy = s_red + 1024;
    float* Rox = s_red + 1536;
    float* Roy = s_red + 2048;
    Rnr[js * 32 + ii] = nr;
    Rsx[js * 32 + ii] = sxv;
    Rsy[js * 32 + ii] = syv;
    Rox[js * 32 + ii] = oxv;
    Roy[js * 32 + ii] = oyv;
    __syncthreads();

    // ---- phase C: per-particle epilogue (32 threads) ----
    if (tid < 32) {
        int ip = blockIdx.x * 32 + tid;
        float Nr = 0.f, Sx = 0.f, Sy = 0.f, Ox = 0.f, Oy = 0.f;
        #pragma unroll
        for (int k = 0; k < NSLOT; k++) {
            Nr += Rnr[k * 32 + tid];
            Sx += Rsx[k * 32 + tid];
            Sy += Rsy[k * 32 + tid];
            Ox += Rox[k * 32 + tid];
            Oy += Roy[k * 32 + tid];
        }
        float px = s_p[ip].x, py = s_p[ip].y;
        float orr = s_o[ip].x, ori = s_o[ip].y;

        float sgn = (Nr > 0.f) ? 1.f : 0.f;
        float den = fmaxf(Nr, 1.f);
        float SSx = Sx / den - px * sgn;
        float SSy = Sy / den - py * sgn;
        float ddx = -SSx, ddy = -SSy;

        float Px = s_cms[0] - px;                // Ps = cms - pos (Ra = inf)
        float Py = s_cms[1] - py;

        float del = deltas[ip];
        float cd = cosf(del), sd = sinf(del);
        float lx = Px * cd - Py * sd;            // Ps * e^{+i delta}
        float ly = Px * sd + Py * cd;
        float rxx = Px * cd + Py * sd;           // Ps * e^{-i delta}
        float ryy = Py * cd - Px * sd;

        float dl = lx * Ox + ly * Oy;
        float dr = rxx * Ox + ryy * Oy;
        float no = fmaxf(__fsqrt_rn(Ox * Ox + Oy * Oy), 1e-14f);
        float cl = dl / (fmaxf(__fsqrt_rn(lx * lx + ly * ly), 1e-14f) * no);
        float cr = dr / (fmaxf(__fsqrt_rn(rxx * rxx + ryy * ryy), 1e-14f) * no);
        bool usel = (cl >= cr);
        float bx = usel ? lx : rxx;
        float by = usel ? ly : ryy;

        bool hasrep = (ddx != 0.f) || (ddy != 0.f);
        float tx = hasrep ? ddx : bx;
        float ty = hasrep ? ddy : by;
        float att = wrapf(atan2f(ty, tx) - atan2f(ori, orr));

        const float CTH  = (float)(0.2 * 25.0 * 0.0028);         // DT*GAMMA*DR
        const float S2DR = (float)0.07483314773547883;           // sqrt(2*DR)
        const float SDT  = (float)0.4472135954999579;            // sqrt(DT)
        float theta = CTH * sinf(att) + rnoise[ip] * S2DR * SDT;
        float rc = cosf(theta), rs = sinf(theta);
        float nore = orr * rc - ori * rs;
        float noim = orr * rs + ori * rc;

        const float CH    = (float)0.7071067811865476;           // sqrt(0.5)
        const float CTT   = (float)1.6733200530681511e-7;        // sqrt(2*DT_TRANS)
        const float DTVEL = (float)(0.2 * 5e-7);                 // DT*VEL
        float tnr = tnre[ip] * CH * CTT;
        float tni = tnim[ip] * CH * CTT;
        g_pos[ip] = make_float2(px + (DTVEL * orr + tnr * SDT),
                                py + (DTVEL * ori + tni * SDT));

        out[(1 * NP + ip) * 2 + 0] = nore;
        out[(1 * NP + ip) * 2 + 1] = noim;
        out[(2 * NP + ip) * 2 + 0] = Ox;
        out[(2 * NP + ip) * 2 + 1] = Oy;
        out[(3 * NP + ip) * 2 + 0] = lx;
        out[(3 * NP + ip) * 2 + 1] = ly;
        out[(4 * NP + ip) * 2 + 0] = rxx;
        out[(4 * NP + ip) * 2 + 1] = ryy;
    }

    // ---- last-block ticket (threadFenceReduction pattern) ----
    __syncthreads();
    if (tid == 0) {
        __threadfence();
        int v = atomicAdd(&g_done, 1);
        s_last = (v == NBLK - 1) ? 1 : 0;
    }
    __syncthreads();
    if (!s_last) return;
    __threadfence();   // acquire all blocks' g_pos / g_nbr / g_cnt writes

    // ---- phase D: collision sweeps in the last block (smem-resident) ----
    float2*         s_pos  = (float2*)smem;                    // 32768
    unsigned short* s_nbr  = (unsigned short*)(smem + 32768);  // 98304 = CAPT*NP*2
    unsigned char*  s_cnt  = (unsigned char*)(smem + 131072);  // 4096

    for (int p = tid; p < NP; p += NTHR) {
        s_pos[p] = g_pos[p];
        int cc = 0;
        #pragma unroll
        for (int slot = 0; slot < NSLOT; slot++) {
            int cnt = g_cnt[p * NSLOT + slot];
            for (int k = 0; k < cnt; k++) {
                unsigned short j = g_nbr[(slot * CAPS + k) * NP + p];
                if (cc < CAPT) s_nbr[cc * NP + p] = j;
                cc++;
            }
        }
        s_cnt[p] = (unsigned char)(cc > CAPT ? CAPT : cc);
    }
    if (tid == 0) s_any = 0;
    __syncthreads();

    const float THR   = (float)(2.0 * 3.15e-6);     // 2*Rc
    const float THR2G = THR * THR * 1.0005f;
    const float MOVC  = (float)(2.1 * 3.15e-6);

    unsigned char myc[8];
    #pragma unroll
    for (int s = 0; s < 8; s++) myc[s] = s_cnt[tid + s * NTHR];

    for (int t = 0; t < 30; t++) {
        float2 mv[8];
        int mycoll = 0;
        #pragma unroll
        for (int s = 0; s < 8; s++) {
            int p = tid + s * NTHR;
            float2 pc = s_pos[p];
            float mx = 0.f, my = 0.f;
            int cnt = myc[s];
            for (int k = 0; k < cnt; k++) {
                int j = s_nbr[k * NP + p];
                float2 q = s_pos[j];
                float dx = q.x - pc.x, dy = q.y - pc.y;   // p_j - p_i
                float r2 = fmaf(dx, dx, dy * dy);
                if (r2 <= THR2G) {
                    float absd = __fsqrt_rn(r2);
                    if (absd <= THR) {
                        float f = (MOVC - absd) * 0.5f;
                        mx += (dx / absd) * f;
                        my += (dy / absd) * f;
                        mycoll = 1;
                    }
                }
            }
            mv[s] = make_float2(pc.x - mx, pc.y - my);
        }
        if (mycoll) atomicOr(&s_any, 1);
        __syncthreads();                 // all reads done; flags visible
        int any = s_any;
        #pragma unroll
        for (int s = 0; s < 8; s++) s_pos[tid + s * NTHR] = mv[s];
        __syncthreads();                 // writes done
        if (!any) break;                 // uniform decision
        if (tid == 0) s_any = 0;
        __syncthreads();                 // reset visible before next atomicOr
    }

    #pragma unroll
    for (int s = 0; s < 8; s++) {
        int p = tid + s * NTHR;
        out[p * 2 + 0] = s_pos[p].x;
        out[p * 2 + 1] = s_pos[p].y;
    }
    if (tid == 0) g_done = 0;            // reset for next graph replay
}

// ---------------------------------------------------------------------------
extern "C" void kernel_launch(void* const* d_in, const int* in_sizes, int n_in,
                              void* d_out, int out_size) {
    const float* pre    = (const float*)d_in[0];
    const float* pim    = (const float*)d_in[1];
    const float* ore    = (const float*)d_in[2];
    const float* oim    = (const float*)d_in[3];
    const float* deltas = (const float*)d_in[4];
    const float* rnoise = (const float*)d_in[5];
    const float* tnre   = (const float*)d_in[6];
    const float* tnim   = (const float*)d_in[7];
    float* out = (float*)d_out;

    cudaFuncSetAttribute(fused_kernel, cudaFuncAttributeMaxDynamicSharedMemorySize, SMEM_BYTES);
    fused_kernel<<<NBLK, NTHR, SMEM_BYTES>>>(pre, pim, ore, oim, deltas, rnoise,
                                             tnre, tnim, out);
}

// round 6
// speedup vs baseline: 7.9335x; 1.3891x over previous
#include <cuda_runtime.h>
#include <math.h>

#define NP    4096
#define NSLOT 32
#define CAPS  6        // per-slot candidate cap (global list)
#define CAPT  16       // per-particle total cap (smem list)
#define NBLK  128
#define NTHR  1024

#define PI_F     3.1415927410125732f
#define TWOPI_F  6.2831854820251465f
#define HALFPI_F 1.5707963705062866f

// scratch (no allocation allowed)
static __device__ float2 g_pos[NP];                        // pos + trans (pre-collision)
static __device__ unsigned short g_nbr[NSLOT * CAPS * NP]; // [slot][k][i]
static __device__ unsigned char  g_cnt[NP * NSLOT];        // [i][slot]
static __device__ int g_done;                              // zero-init; reset by sweep block

__device__ __forceinline__ float wrapf(float d) {
    // replicates: where(d <= -pi, jnp.mod(d, pi), d); then d -= (d >= pi) * 2pi
    if (d <= -PI_F) {
        float r = fmodf(d, PI_F);
        if (r < 0.f) r += PI_F;          // python-mod sign fix
        d = r;
    }
    if (d >= PI_F) d -= TWOPI_F;
    return d;
}

// smem union:
//  pair view : s_p[NP] float2 (32KB) | s_o[NP] float2 (32KB) | s_ag[NP] (16KB) | s_red 5*1024 (20KB)
//  sweep view: s_pos[NP] float2 (32KB) | s_nbr[CAPT*NP] u16 (128KB) | s_cnt[NP] u8 (4KB)
#define SMEM_BYTES (32768 + 131072 + 4096)   // 167936

__global__ void __launch_bounds__(NTHR, 1)
fused_kernel(const float* __restrict__ pre, const float* __restrict__ pim,
             const float* __restrict__ ore, const float* __restrict__ oim,
             const float* __restrict__ deltas, const float* __restrict__ rnoise,
             const float* __restrict__ tnre, const float* __restrict__ tnim,
             float* __restrict__ out) {
    extern __shared__ char smem[];
    float2* s_p  = (float2*)smem;                    // 32768
    float2* s_o  = (float2*)(smem + 32768);          // 32768
    float*  s_ag = (float*)(smem + 65536);           // 16384
    float*  s_red = (float*)(smem + 81920);          // 20480

    __shared__ float s_cms[2];
    __shared__ int s_last, s_any;

    int tid = threadIdx.x;

    // ---- phase A: load + angles + cms (per-block, deterministic order) ----
    float ax = 0.f, ay = 0.f;
    for (int k = tid; k < NP; k += NTHR) {
        float px = pre[k], py = pim[k];
        s_p[k] = make_float2(px, py);
        float oxr = ore[k], oyi = oim[k];
        s_o[k] = make_float2(oxr, oyi);
        s_ag[k] = atan2f(oyi, oxr);
        ax += px; ay += py;
    }
    s_red[tid] = ax; s_red[NTHR + tid] = ay;
    __syncthreads();
    for (int s = NTHR / 2; s > 0; s >>= 1) {
        if (tid < s) { s_red[tid] += s_red[tid + s]; s_red[NTHR + tid] += s_red[NTHR + tid + s]; }
        __syncthreads();
    }
    if (tid == 0) {
        s_cms[0] = s_red[0] * (1.0f / NP);     // n_a = 4096 exactly
        s_cms[1] = s_red[NTHR] * (1.0f / NP);
    }
    __syncthreads();

    // ---- phase B: pairwise scan.  32 j-slots x 32 i-lanes ----
    int ii = tid & 31, js = tid >> 5;
    int i = blockIdx.x * 32 + ii;
    float pxi = s_p[i].x, pyi = s_p[i].y, agi = s_ag[i];

    const float ROCf  = (float)(2.5e-5 + 3.15e-6);   // RO + RC = 28.15um
    const float ROC2G = ROCf * ROCf * 1.0005f;       // squared prefilter w/ guard
    const float RRf   = (float)(8e-6);
    const float RCAP  = (float)(6.0 * 3.15e-6);      // collision capture radius 6*Rc
    const float RCAP2 = RCAP * RCAP;

    float nr = 0.f, sxv = 0.f, syv = 0.f, oxv = 0.f, oyv = 0.f;
    int c = 0;

    for (int j = js; j < NP; j += NSLOT) {
        float2 pj = s_p[j];
        float dx = pxi - pj.x, dy = pyi - pj.y;
        float r2 = fmaf(dx, dx, dy * dy);
        bool same = (j == i);
        if (r2 <= ROC2G || same) {
            if (r2 <= RCAP2 && !same) {                 // collision candidate
                if (c < CAPS) g_nbr[(js * CAPS + c) * NP + i] = (unsigned short)j;
                c++;
            }
            float dist = same ? 1.0f : __fsqrt_rn(r2);  // diag dist = 1 (eye)
            if (dist <= ROCf || same) {                 // mask_ro (self included)
                oxv += s_o[j].x;
                oyv += s_o[j].y;
            }
            if (dist <= RRf && !same) {                 // mask_rr (self excluded)
                float ad = agi - s_ag[j];
                if (ad <= -PI_F) { float r = fmodf(ad, PI_F); if (r < 0.f) r += PI_F; ad = r; }
                if (ad >= PI_F) ad -= TWOPI_F;
                if (fabsf(ad) < HALFPI_F) {             // in_front
                    nr += 1.0f; sxv += pj.x; syv += pj.y;
                }
            }
        }
    }
    g_cnt[i * NSLOT + js] = (unsigned char)(c > CAPS ? CAPS : c);

    // partial reduction across the 32 j-slots
    float* Rnr = s_red;
    float* Rsx = s_red + NTHR;
    float* Rsy = s_red + 2 * NTHR;
    float* Rox = s_red + 3 * NTHR;
    float* Roy = s_red + 4 * NTHR;
    Rnr[js * 32 + ii] = nr;
    Rsx[js * 32 + ii] = sxv;
    Rsy[js * 32 + ii] = syv;
    Rox[js * 32 + ii] = oxv;
    Roy[js * 32 + ii] = oyv;
    __syncthreads();

    // ---- phase C: per-particle epilogue (32 threads) ----
    if (tid < 32) {
        int ip = blockIdx.x * 32 + tid;
        float Nr = 0.f, Sx = 0.f, Sy = 0.f, Ox = 0.f, Oy = 0.f;
        #pragma unroll
        for (int k = 0; k < NSLOT; k++) {
            Nr += Rnr[k * 32 + tid];
            Sx += Rsx[k * 32 + tid];
            Sy += Rsy[k * 32 + tid];
            Ox += Rox[k * 32 + tid];
            Oy += Roy[k * 32 + tid];
        }
        float px = s_p[ip].x, py = s_p[ip].y;
        float orr = s_o[ip].x, ori = s_o[ip].y;

        float sgn = (Nr > 0.f) ? 1.f : 0.f;
        float den = fmaxf(Nr, 1.f);
        float SSx = Sx / den - px * sgn;
        float SSy = Sy / den - py * sgn;
        float ddx = -SSx, ddy = -SSy;

        float Px = s_cms[0] - px;                // Ps = cms - pos (Ra = inf)
        float Py = s_cms[1] - py;

        float del = deltas[ip];
        float cd = cosf(del), sd = sinf(del);
        float lx = Px * cd - Py * sd;            // Ps * e^{+i delta}
        float ly = Px * sd + Py * cd;
        float rxx = Px * cd + Py * sd;           // Ps * e^{-i delta}
        float ryy = Py * cd - Px * sd;

        float dl = lx * Ox + ly * Oy;
        float dr = rxx * Ox + ryy * Oy;
        float no = fmaxf(__fsqrt_rn(Ox * Ox + Oy * Oy), 1e-14f);
        float cl = dl / (fmaxf(__fsqrt_rn(lx * lx + ly * ly), 1e-14f) * no);
        float cr = dr / (fmaxf(__fsqrt_rn(rxx * rxx + ryy * ryy), 1e-14f) * no);
        bool usel = (cl >= cr);
        float bx = usel ? lx : rxx;
        float by = usel ? ly : ryy;

        bool hasrep = (ddx != 0.f) || (ddy != 0.f);
        float tx = hasrep ? ddx : bx;
        float ty = hasrep ? ddy : by;
        float att = wrapf(atan2f(ty, tx) - atan2f(ori, orr));

        const float CTH  = (float)(0.2 * 25.0 * 0.0028);         // DT*GAMMA*DR
        const float S2DR = (float)0.07483314773547883;           // sqrt(2*DR)
        const float SDT  = (float)0.4472135954999579;            // sqrt(DT)
        float theta = CTH * sinf(att) + rnoise[ip] * S2DR * SDT;
        float rc = cosf(theta), rs = sinf(theta);
        float nore = orr * rc - ori * rs;
        float noim = orr * rs + ori * rc;

        const float CH    = (float)0.7071067811865476;           // sqrt(0.5)
        const float CTT   = (float)1.6733200530681511e-7;        // sqrt(2*DT_TRANS)
        const float DTVEL = (float)(0.2 * 5e-7);                 // DT*VEL
        float tnr = tnre[ip] * CH * CTT;
        float tni = tnim[ip] * CH * CTT;
        g_pos[ip] = make_float2(px + (DTVEL * orr + tnr * SDT),
                                py + (DTVEL * ori + tni * SDT));

        out[(1 * NP + ip) * 2 + 0] = nore;
        out[(1 * NP + ip) * 2 + 1] = noim;
        out[(2 * NP + ip) * 2 + 0] = Ox;
        out[(2 * NP + ip) * 2 + 1] = Oy;
        out[(3 * NP + ip) * 2 + 0] = lx;
        out[(3 * NP + ip) * 2 + 1] = ly;
        out[(4 * NP + ip) * 2 + 0] = rxx;
        out[(4 * NP + ip) * 2 + 1] = ryy;
    }

    // ---- last-block ticket (threadFenceReduction pattern) ----
    __syncthreads();
    if (tid == 0) {
        __threadfence();
        int v = atomicAdd(&g_done, 1);
        s_last = (v == NBLK - 1) ? 1 : 0;
    }
    __syncthreads();
    if (!s_last) return;
    __threadfence();   // acquire all blocks' g_pos / g_nbr / g_cnt writes

    // ---- phase D: collision sweeps in the last block (smem-resident) ----
    float2*         s_pos = (float2*)smem;                    // 32768
    unsigned short* s_nbr = (unsigned short*)(smem + 32768);  // 131072 = CAPT*NP*2
    unsigned char*  s_cnt = (unsigned char*)(smem + 163840);  // 4096

    for (int p = tid; p < NP; p += NTHR) {
        s_pos[p] = g_pos[p];
        int cc = 0;
        #pragma unroll
        for (int slot = 0; slot < NSLOT; slot++) {
            int cnt = g_cnt[p * NSLOT + slot];
            for (int k = 0; k < cnt; k++) {
                unsigned short j = g_nbr[(slot * CAPS + k) * NP + p];
                if (cc < CAPT) s_nbr[cc * NP + p] = j;
                cc++;
            }
        }
        s_cnt[p] = (unsigned char)(cc > CAPT ? CAPT : cc);
    }
    if (tid == 0) s_any = 0;
    __syncthreads();

    const float THR   = (float)(2.0 * 3.15e-6);     // 2*Rc
    const float THR2G = THR * THR * 1.0005f;
    const float MOVC  = (float)(2.1 * 3.15e-6);

    unsigned char myc[4];
    #pragma unroll
    for (int s = 0; s < 4; s++) myc[s] = s_cnt[tid + s * NTHR];

    for (int t = 0; t < 30; t++) {
        float2 mv[4];
        int mycoll = 0;
        #pragma unroll
        for (int s = 0; s < 4; s++) {
            int p = tid + s * NTHR;
            float2 pc = s_pos[p];
            float mx = 0.f, my = 0.f;
            int cnt = myc[s];
            for (int k = 0; k < cnt; k++) {
                int j = s_nbr[k * NP + p];
                float2 q = s_pos[j];
                float dx = q.x - pc.x, dy = q.y - pc.y;   // p_j - p_i
                float r2 = fmaf(dx, dx, dy * dy);
                if (r2 <= THR2G) {
                    float rinv = __frsqrt_rn(r2);
                    float absd = r2 * rinv;
                    if (absd <= THR) {
                        float f = (MOVC - absd) * 0.5f * rinv;
                        mx += dx * f;
                        my += dy * f;
                        mycoll = 1;
                    }
                }
            }
            mv[s] = make_float2(pc.x - mx, pc.y - my);
        }
        if (mycoll) atomicOr(&s_any, 1);
        __syncthreads();                 // all reads done; flags visible
        int any = s_any;
        #pragma unroll
        for (int s = 0; s < 4; s++) s_pos[tid + s * NTHR] = mv[s];
        __syncthreads();                 // writes done
        if (!any) break;                 // uniform decision
        if (tid == 0) s_any = 0;
        __syncthreads();                 // reset visible before next atomicOr
    }

    #pragma unroll
    for (int s = 0; s < 4; s++) {
        int p = tid + s * NTHR;
        out[p * 2 + 0] = s_pos[p].x;
        out[p * 2 + 1] = s_pos[p].y;
    }
    if (tid == 0) g_done = 0;            // reset for next graph replay
}

// ---------------------------------------------------------------------------
extern "C" void kernel_launch(void* const* d_in, const int* in_sizes, int n_in,
                              void* d_out, int out_size) {
    const float* pre    = (const float*)d_in[0];
    const float* pim    = (const float*)d_in[1];
    const float* ore    = (const float*)d_in[2];
    const float* oim    = (const float*)d_in[3];
    const float* deltas = (const float*)d_in[4];
    const float* rnoise = (const float*)d_in[5];
    const float* tnre   = (const float*)d_in[6];
    const float* tnim   = (const float*)d_in[7];
    float* out = (float*)d_out;

    cudaFuncSetAttribute(fused_kernel, cudaFuncAttributeMaxDynamicSharedMemorySize, SMEM_BYTES);
    fused_kernel<<<NBLK, NTHR, SMEM_BYTES>>>(pre, pim, ore, oim, deltas, rnoise,
                                             tnre, tnim, out);
}

// round 7
// speedup vs baseline: 9.3613x; 1.1800x over previous
#include <cuda_runtime.h>
#include <math.h>

#define NP    4096
#define NSLOT 32
#define CHUNK 128      // NP / NSLOT, contiguous j per warp
#define CAPS  6        // per-slot candidate cap (global list)
#define CAPT  12       // per-particle total cap (smem list)
#define NBLK  128
#define NTHR  1024

#define PI_F     3.1415927410125732f
#define TWOPI_F  6.2831854820251465f
#define HALFPI_F 1.5707963705062866f

// scratch (no allocation allowed)
static __device__ float2 g_pos[NP];                        // pos + trans (pre-collision)
static __device__ unsigned short g_nbr[NSLOT * CAPS * NP]; // [slot][k][i]
static __device__ unsigned char  g_cnt[NP * NSLOT];        // [i][slot]
static __device__ int g_done;                              // zero-init; reset by sweep block

__device__ __forceinline__ float wrapf(float d) {
    // replicates: where(d <= -pi, jnp.mod(d, pi), d); then d -= (d >= pi) * 2pi
    if (d <= -PI_F) {
        float r = fmodf(d, PI_F);
        if (r < 0.f) r += PI_F;          // python-mod sign fix
        d = r;
    }
    if (d >= PI_F) d -= TWOPI_F;
    return d;
}

// smem union:
//  pair view : s_p[NP] f2 (32KB) | s_o[NP] f2 (32KB) | s_ag[NP] (16KB) | s_red 5*1024 (20KB) = 100KB
//  sweep view: s_pos[NP] f2 (32KB) | s_nbr[CAPT*NP] u16 (96KB) | s_cnt[NP] u8 (4KB) = 132KB
#define SMEM_BYTES (32768 + 98304 + 4096)   // 135168

__global__ void __launch_bounds__(NTHR, 1)
fused_kernel(const float* __restrict__ pre, const float* __restrict__ pim,
             const float* __restrict__ ore, const float* __restrict__ oim,
             const float* __restrict__ deltas, const float* __restrict__ rnoise,
             const float* __restrict__ tnre, const float* __restrict__ tnim,
             float* __restrict__ out) {
    extern __shared__ char smem[];
    float2* s_p  = (float2*)smem;                    // 32768
    float2* s_o  = (float2*)(smem + 32768);          // 32768
    float*  s_ag = (float*)(smem + 65536);           // 16384
    float*  s_red = (float*)(smem + 81920);          // 20480

    __shared__ float s_cms[2];
    __shared__ int s_last;

    int tid = threadIdx.x;

    // ---- phase A: load + angles + cms (per-block, deterministic order) ----
    float ax = 0.f, ay = 0.f;
    for (int k = tid; k < NP; k += NTHR) {
        float px = pre[k], py = pim[k];
        s_p[k] = make_float2(px, py);
        float oxr = ore[k], oyi = oim[k];
        s_o[k] = make_float2(oxr, oyi);
        s_ag[k] = atan2f(oyi, oxr);
        ax += px; ay += py;
    }
    s_red[tid] = ax; s_red[NTHR + tid] = ay;
    __syncthreads();
    for (int s = NTHR / 2; s > 0; s >>= 1) {
        if (tid < s) { s_red[tid] += s_red[tid + s]; s_red[NTHR + tid] += s_red[NTHR + tid + s]; }
        __syncthreads();
    }
    if (tid == 0) {
        s_cms[0] = s_red[0] * (1.0f / NP);     // n_a = 4096 exactly
        s_cms[1] = s_red[NTHR] * (1.0f / NP);
    }
    __syncthreads();

    // ---- phase B: pairwise scan.  32 warps x contiguous 128-j chunks ----
    int ii = tid & 31, js = tid >> 5;
    int i = blockIdx.x * 32 + ii;
    float pxi = s_p[i].x, pyi = s_p[i].y, agi = s_ag[i];

    const float ROCf  = (float)(2.5e-5 + 3.15e-6);   // RO + RC = 28.15um
    const float ROC2G = ROCf * ROCf * 1.0005f;       // squared prefilter w/ guard
    const float RRf   = (float)(8e-6);
    const float RCAP  = (float)(4.5 * 3.15e-6);      // collision capture radius 4.5*Rc
    const float RCAP2 = RCAP * RCAP;

    float nr = 0.f, sxv = 0.f, syv = 0.f, oxv = 0.f, oyv = 0.f;
    int c = 0;
    int base = js * CHUNK;
    const float4* s_p4 = (const float4*)s_p;

    #pragma unroll 2
    for (int jj = 0; jj < CHUNK; jj += 2) {
        int j0 = base + jj;
        float4 pp = s_p4[j0 >> 1];          // particles j0, j0+1
        #pragma unroll
        for (int h = 0; h < 2; h++) {
            int j = j0 + h;
            float pjx = h ? pp.z : pp.x;
            float pjy = h ? pp.w : pp.y;
            float dx = pxi - pjx, dy = pyi - pjy;
            float r2 = fmaf(dx, dx, dy * dy);
            bool same = (j == i);
            if (r2 <= ROC2G || same) {
                if (r2 <= RCAP2 && !same) {                 // collision candidate
                    if (c < CAPS) g_nbr[(js * CAPS + c) * NP + i] = (unsigned short)j;
                    c++;
                }
                float dist = same ? 1.0f : __fsqrt_rn(r2);  // diag dist = 1 (eye)
                if (dist <= ROCf || same) {                 // mask_ro (self included)
                    oxv += s_o[j].x;
                    oyv += s_o[j].y;
                }
                if (dist <= RRf && !same) {                 // mask_rr (self excluded)
                    float ad = agi - s_ag[j];
                    if (ad <= -PI_F) { float r = fmodf(ad, PI_F); if (r < 0.f) r += PI_F; ad = r; }
                    if (ad >= PI_F) ad -= TWOPI_F;
                    if (fabsf(ad) < HALFPI_F) {             // in_front
                        nr += 1.0f; sxv += pjx; syv += pjy;
                    }
                }
            }
        }
    }
    g_cnt[i * NSLOT + js] = (unsigned char)(c > CAPS ? CAPS : c);

    // partial reduction across the 32 j-slots
    float* Rnr = s_red;
    float* Rsx = s_red + NTHR;
    float* Rsy = s_red + 2 * NTHR;
    float* Rox = s_red + 3 * NTHR;
    float* Roy = s_red + 4 * NTHR;
    Rnr[js * 32 + ii] = nr;
    Rsx[js * 32 + ii] = sxv;
    Rsy[js * 32 + ii] = syv;
    Rox[js * 32 + ii] = oxv;
    Roy[js * 32 + ii] = oyv;
    __syncthreads();

    // ---- phase C: per-particle epilogue (32 threads) ----
    if (tid < 32) {
        int ip = blockIdx.x * 32 + tid;
        float Nr = 0.f, Sx = 0.f, Sy = 0.f, Ox = 0.f, Oy = 0.f;
        #pragma unroll
        for (int k = 0; k < NSLOT; k++) {
            Nr += Rnr[k * 32 + tid];
            Sx += Rsx[k * 32 + tid];
            Sy += Rsy[k * 32 + tid];
            Ox += Rox[k * 32 + tid];
            Oy += Roy[k * 32 + tid];
        }
        float px = s_p[ip].x, py = s_p[ip].y;
        float orr = s_o[ip].x, ori = s_o[ip].y;

        float sgn = (Nr > 0.f) ? 1.f : 0.f;
        float den = fmaxf(Nr, 1.f);
        float SSx = Sx / den - px * sgn;
        float SSy = Sy / den - py * sgn;
        float ddx = -SSx, ddy = -SSy;

        float Px = s_cms[0] - px;                // Ps = cms - pos (Ra = inf)
        float Py = s_cms[1] - py;

        float del = deltas[ip];
        float cd = cosf(del), sd = sinf(del);
        float lx = Px * cd - Py * sd;            // Ps * e^{+i delta}
        float ly = Px * sd + Py * cd;
        float rxx = Px * cd + Py * sd;           // Ps * e^{-i delta}
        float ryy = Py * cd - Px * sd;

        float dl = lx * Ox + ly * Oy;
        float dr = rxx * Ox + ryy * Oy;
        float no = fmaxf(__fsqrt_rn(Ox * Ox + Oy * Oy), 1e-14f);
        float cl = dl / (fmaxf(__fsqrt_rn(lx * lx + ly * ly), 1e-14f) * no);
        float cr = dr / (fmaxf(__fsqrt_rn(rxx * rxx + ryy * ryy), 1e-14f) * no);
        bool usel = (cl >= cr);
        float bx = usel ? lx : rxx;
        float by = usel ? ly : ryy;

        bool hasrep = (ddx != 0.f) || (ddy != 0.f);
        float tx = hasrep ? ddx : bx;
        float ty = hasrep ? ddy : by;
        float att = wrapf(atan2f(ty, tx) - atan2f(ori, orr));

        const float CTH  = (float)(0.2 * 25.0 * 0.0028);         // DT*GAMMA*DR
        const float S2DR = (float)0.07483314773547883;           // sqrt(2*DR)
        const float SDT  = (float)0.4472135954999579;            // sqrt(DT)
        float theta = CTH * sinf(att) + rnoise[ip] * S2DR * SDT;
        float rc = cosf(theta), rs = sinf(theta);
        float nore = orr * rc - ori * rs;
        float noim = orr * rs + ori * rc;

        const float CH    = (float)0.7071067811865476;           // sqrt(0.5)
        const float CTT   = (float)1.6733200530681511e-7;        // sqrt(2*DT_TRANS)
        const float DTVEL = (float)(0.2 * 5e-7);                 // DT*VEL
        float tnr = tnre[ip] * CH * CTT;
        float tni = tnim[ip] * CH * CTT;
        g_pos[ip] = make_float2(px + (DTVEL * orr + tnr * SDT),
                                py + (DTVEL * ori + tni * SDT));

        out[(1 * NP + ip) * 2 + 0] = nore;
        out[(1 * NP + ip) * 2 + 1] = noim;
        out[(2 * NP + ip) * 2 + 0] = Ox;
        out[(2 * NP + ip) * 2 + 1] = Oy;
        out[(3 * NP + ip) * 2 + 0] = lx;
        out[(3 * NP + ip) * 2 + 1] = ly;
        out[(4 * NP + ip) * 2 + 0] = rxx;
        out[(4 * NP + ip) * 2 + 1] = ryy;
    }

    // ---- last-block ticket (threadFenceReduction pattern) ----
    __syncthreads();
    if (tid == 0) {
        __threadfence();
        int v = atomicAdd(&g_done, 1);
        s_last = (v == NBLK - 1) ? 1 : 0;
    }
    __syncthreads();
    if (!s_last) return;
    __threadfence();   // acquire all blocks' g_pos / g_nbr / g_cnt writes

    // ---- phase D: collision sweeps in the last block (smem-resident) ----
    float2*         s_pos = (float2*)smem;                    // 32768
    unsigned short* s_nbr = (unsigned short*)(smem + 32768);  // 98304 = CAPT*NP*2
    unsigned char*  s_cnt = (unsigned char*)(smem + 131072);  // 4096

    for (int p = tid; p < NP; p += NTHR) {
        s_pos[p] = g_pos[p];
        int cc = 0;
        #pragma unroll
        for (int slot = 0; slot < NSLOT; slot++) {
            int cnt = g_cnt[p * NSLOT + slot];
            for (int k = 0; k < cnt; k++) {
                unsigned short j = g_nbr[(slot * CAPS + k) * NP + p];
                if (cc < CAPT) s_nbr[cc * NP + p] = j;
                cc++;
            }
        }
        s_cnt[p] = (unsigned char)(cc > CAPT ? CAPT : cc);
    }
    __syncthreads();

    const float THR   = (float)(2.0 * 3.15e-6);     // 2*Rc
    const float THR2G = THR * THR * 1.0005f;
    const float MOVC  = (float)(2.1 * 3.15e-6);

    unsigned char myc[4];
    #pragma unroll
    for (int s = 0; s < 4; s++) myc[s] = s_cnt[tid + s * NTHR];

    for (int t = 0; t < 30; t++) {
        float2 mv[4];
        int mycoll = 0;
        #pragma unroll
        for (int s = 0; s < 4; s++) {
            int p = tid + s * NTHR;
            float2 pc = s_pos[p];
            float mx = 0.f, my = 0.f;
            int cnt = myc[s];
            for (int k = 0; k < cnt; k++) {
                int j = s_nbr[k * NP + p];
                float2 q = s_pos[j];
                float dx = q.x - pc.x, dy = q.y - pc.y;   // p_j - p_i
                float r2 = fmaf(dx, dx, dy * dy);
                if (r2 <= THR2G) {
                    float rinv = __frsqrt_rn(r2);
                    float absd = r2 * rinv;
                    if (absd <= THR) {
                        float f = (MOVC - absd) * 0.5f * rinv;
                        mx += dx * f;
                        my += dy * f;
                        mycoll = 1;
                    }
                }
            }
            mv[s] = make_float2(pc.x - mx, pc.y - my);
        }
        int any = __syncthreads_or(mycoll);   // barrier: all reads done + flag reduced
        #pragma unroll
        for (int s = 0; s < 4; s++) s_pos[tid + s * NTHR] = mv[s];
        __syncthreads();                      // writes visible
        if (!any) break;                      // uniform decision
    }

    #pragma unroll
    for (int s = 0; s < 4; s++) {
        int p = tid + s * NTHR;
        out[p * 2 + 0] = s_pos[p].x;
        out[p * 2 + 1] = s_pos[p].y;
    }
    if (tid == 0) g_done = 0;            // reset for next graph replay
}

// ---------------------------------------------------------------------------
extern "C" void kernel_launch(void* const* d_in, const int* in_sizes, int n_in,
                              void* d_out, int out_size) {
    const float* pre    = (const float*)d_in[0];
    const float* pim    = (const float*)d_in[1];
    const float* ore    = (const float*)d_in[2];
    const float* oim    = (const float*)d_in[3];
    const float* deltas = (const float*)d_in[4];
    const float* rnoise = (const float*)d_in[5];
    const float* tnre   = (const float*)d_in[6];
    const float* tnim   = (const float*)d_in[7];
    float* out = (float*)d_out;

    cudaFuncSetAttribute(fused_kernel, cudaFuncAttributeMaxDynamicSharedMemorySize, SMEM_BYTES);
    fused_kernel<<<NBLK, NTHR, SMEM_BYTES>>>(pre, pim, ore, oim, deltas, rnoise,
                                             tnre, tnim, out);
}

// round 9
// speedup vs baseline: 9.5729x; 1.0226x over previous
#include <cuda_runtime.h>
#include <math.h>

#define NP    4096
#define NTHR  1024
#define SEGS  4        // NP / NTHR particles per thread
#define NC    45       // cells per side
#define NCELL 2025
#define CPAD  2048
#define CAPT  12       // per-particle collision candidate cap

#define PI_F     3.1415927410125732f
#define TWOPI_F  6.2831854820251465f
#define HALFPI_F 1.5707963705062866f

// smem layout (bytes)
//      0  s_p      float2[NP]   32768
//  32768  s_o      float2[NP]   32768
//  65536  s_ag     float [NP]   16384
//  81920  s_cellof u16   [NP]    8192
//  90112  s_scan   u32 [CPAD]    8192   (inclusive scan of counts)
//  98304  s_cur    u32 [CPAD]    8192   (counts -> scatter cursor)
// 106496  s_srt    u16   [NP]    8192   (cell-sorted particle ids)
// 114688  s_nbr    u16[CAPT*NP] 98304
// 212992  s_red    float[2048]   8192
#define SMEM_BYTES 221184

__global__ void __launch_bounds__(NTHR, 1)
fused_kernel(const float* __restrict__ pre, const float* __restrict__ pim,
             const float* __restrict__ ore, const float* __restrict__ oim,
             const float* __restrict__ deltas, const float* __restrict__ rnoise,
             const float* __restrict__ tnre, const float* __restrict__ tnim,
             float* __restrict__ out) {
    extern __shared__ char smem[];
    float2*         s_p      = (float2*)smem;
    float2*         s_o      = (float2*)(smem + 32768);
    float*          s_ag     = (float*)(smem + 65536);
    unsigned short* s_cellof = (unsigned short*)(smem + 81920);
    unsigned int*   s_scan   = (unsigned int*)(smem + 90112);
    unsigned int*   s_cur    = (unsigned int*)(smem + 98304);
    unsigned short* s_srt    = (unsigned short*)(smem + 106496);
    unsigned short* s_nbr    = (unsigned short*)(smem + 114688);
    float*          s_red    = (float*)(smem + 212992);

    __shared__ float s_cms[2];

    int tid = threadIdx.x;
    const float INV_CELL = (float)NC / 1.28e-3f;

    // ---- phase A: zero counts, load inputs, histogram, cms partials ----
    s_cur[tid] = 0u; s_cur[tid + NTHR] = 0u;
    __syncthreads();

    float ax = 0.f, ay = 0.f;
    #pragma unroll
    for (int s = 0; s < SEGS; s++) {
        int k = tid + s * NTHR;
        float px = pre[k], py = pim[k];
        s_p[k] = make_float2(px, py);
        float oxr = ore[k], oyi = oim[k];
        s_o[k] = make_float2(oxr, oyi);
        s_ag[k] = atan2f(oyi, oxr);
        int cx = (int)(px * INV_CELL); cx = cx < 0 ? 0 : (cx > NC - 1 ? NC - 1 : cx);
        int cy = (int)(py * INV_CELL); cy = cy < 0 ? 0 : (cy > NC - 1 ? NC - 1 : cy);
        int cell = cy * NC + cx;
        s_cellof[k] = (unsigned short)cell;
        atomicAdd(&s_cur[cell], 1u);
        ax += px; ay += py;
    }
    s_red[tid] = ax; s_red[NTHR + tid] = ay;
    __syncthreads();
    for (int s = NTHR / 2; s > 0; s >>= 1) {
        if (tid < s) { s_red[tid] += s_red[tid + s]; s_red[NTHR + tid] += s_red[NTHR + tid + s]; }
        __syncthreads();
    }
    if (tid == 0) {
        s_cms[0] = s_red[0] * (1.0f / NP);     // n_a = 4096 exactly
        s_cms[1] = s_red[NTHR] * (1.0f / NP);
    }

    // ---- binning: inclusive scan (Hillis-Steele, 2048 elems) + scatter ----
    s_scan[tid] = s_cur[tid];
    s_scan[tid + NTHR] = s_cur[tid + NTHR];
    __syncthreads();
    for (int off = 1; off < CPAD; off <<= 1) {
        unsigned v0 = (tid >= off) ? s_scan[tid - off] : 0u;
        unsigned v1 = s_scan[tid + NTHR - off];          // tid+1024 >= off always
        __syncthreads();
        s_scan[tid] += v0;
        s_scan[tid + NTHR] += v1;
        __syncthreads();
    }
    // cursor = exclusive start
    {
        unsigned c0 = s_cur[tid], c1 = s_cur[tid + NTHR];
        s_cur[tid] = s_scan[tid] - c0;
        s_cur[tid + NTHR] = s_scan[tid + NTHR] - c1;
    }
    __syncthreads();
    #pragma unroll
    for (int s = 0; s < SEGS; s++) {
        int k = tid + s * NTHR;
        unsigned pos = atomicAdd(&s_cur[s_cellof[k]], 1u);
        s_srt[pos] = (unsigned short)k;
    }
    __syncthreads();

    // ---- phase B + epilogue: per-thread, 4 particles, 3x3 cells each ----
    const float ROCf  = (float)(2.5e-5 + 3.15e-6);   // RO + RC = 28.15um
    const float ROC2G = ROCf * ROCf * 1.0005f;       // squared prefilter w/ guard
    const float RRf   = (float)(8e-6);
    const float RCAP  = (float)(4.5 * 3.15e-6);      // collision capture radius
    const float RCAP2 = RCAP * RCAP;

    float npx[SEGS], npy[SEGS];
    int   myc[SEGS];

    #pragma unroll
    for (int s = 0; s < SEGS; s++) {
        int i = tid + s * NTHR;
        float pxi = s_p[i].x, pyi = s_p[i].y, agi = s_ag[i];
        int cell = s_cellof[i];
        int cx = cell % NC, cy = cell / NC;
        int x0 = cx > 0 ? cx - 1 : 0, x1 = cx < NC - 1 ? cx + 1 : NC - 1;
        int y0 = cy > 0 ? cy - 1 : 0, y1 = cy < NC - 1 ? cy + 1 : NC - 1;

        float nr = 0.f, sxv = 0.f, syv = 0.f, oxv = 0.f, oyv = 0.f;
        int cc = 0;

        for (int gy = y0; gy <= y1; gy++) {
            for (int gx = x0; gx <= x1; gx++) {
                int c = gy * NC + gx;
                int b = (c == 0) ? 0 : (int)s_scan[c - 1];
                int e = (int)s_scan[c];
                for (int k = b; k < e; k++) {
                    int j = s_srt[k];
                    float2 pj = s_p[j];
                    float dx = pxi - pj.x, dy = pyi - pj.y;
                    float r2 = fmaf(dx, dx, dy * dy);
                    bool same = (j == i);
                    if (r2 <= ROC2G || same) {
                        if (r2 <= RCAP2 && !same) {                 // collision candidate
                            if (cc < CAPT) s_nbr[cc * NP + i] = (unsigned short)j;
                            cc++;
                        }
                        float dist = same ? 1.0f : __fsqrt_rn(r2);  // diag dist = 1 (eye)
                        if (dist <= ROCf || same) {                 // mask_ro (self incl.)
                            oxv += s_o[j].x;
                            oyv += s_o[j].y;
                        }
                        if (dist <= RRf && !same) {                 // mask_rr (self excl.)
                            float ad = agi - s_ag[j];
                            if (ad <= -PI_F) { float r = fmodf(ad, PI_F); if (r < 0.f) r += PI_F; ad = r; }
                            if (ad >= PI_F) ad -= TWOPI_F;
                            if (fabsf(ad) < HALFPI_F) {             // in_front
                                nr += 1.0f; sxv += pj.x; syv += pj.y;
                            }
                        }
                    }
                }
            }
        }
        myc[s] = cc > CAPT ? CAPT : cc;

        // ---- epilogue for particle i ----
        float orr = s_o[i].x, ori = s_o[i].y;

        float sgn = (nr > 0.f) ? 1.f : 0.f;
        float den = fmaxf(nr, 1.f);
        float SSx = sxv / den - pxi * sgn;
        float SSy = syv / den - pyi * sgn;
        float ddx = -SSx, ddy = -SSy;

        float Px = s_cms[0] - pxi;               // Ps = cms - pos (Ra = inf)
        float Py = s_cms[1] - pyi;

        float del = deltas[i];
        float cd = cosf(del), sd = sinf(del);
        float lx = Px * cd - Py * sd;            // Ps * e^{+i delta}
        float ly = Px * sd + Py * cd;
        float rxx = Px * cd + Py * sd;           // Ps * e^{-i delta}
        float ryy = Py * cd - Px * sd;

        float dl = lx * oxv + ly * oyv;
        float dr = rxx * oxv + ryy * oyv;
        float no = fmaxf(__fsqrt_rn(oxv * oxv + oyv * oyv), 1e-14f);
        float cl = dl / (fmaxf(__fsqrt_rn(lx * lx + ly * ly), 1e-14f) * no);
        float cr = dr / (fmaxf(__fsqrt_rn(rxx * rxx + ryy * ryy), 1e-14f) * no);
        bool usel = (cl >= cr);
        float bx = usel ? lx : rxx;
        float by = usel ? ly : ryy;

        bool hasrep = (ddx != 0.f) || (ddy != 0.f);
        float tx = hasrep ? ddx : bx;
        float ty = hasrep ? ddy : by;
        float att_d = atan2f(ty, tx) - atan2f(ori, orr);
        if (att_d <= -PI_F) { float r = fmodf(att_d, PI_F); if (r < 0.f) r += PI_F; att_d = r; }
        if (att_d >= PI_F) att_d -= TWOPI_F;

        const float CTH  = (float)(0.2 * 25.0 * 0.0028);         // DT*GAMMA*DR
        const float S2DR = (float)0.07483314773547883;           // sqrt(2*DR)
        const float SDT  = (float)0.4472135954999579;            // sqrt(DT)
        float theta = CTH * sinf(att_d) + rnoise[i] * S2DR * SDT;
        float rc = cosf(theta), rs = sinf(theta);
        float nore = orr * rc - ori * rs;
        float noim = orr * rs + ori * rc;

        const float CH    = (float)0.7071067811865476;           // sqrt(0.5)
        const float CTT   = (float)1.6733200530681511e-7;        // sqrt(2*DT_TRANS)
        const float DTVEL = (float)(0.2 * 5e-7);                 // DT*VEL
        float tnr = tnre[i] * CH * CTT;
        float tni = tnim[i] * CH * CTT;
        npx[s] = pxi + (DTVEL * orr + tnr * SDT);
        npy[s] = pyi + (DTVEL * ori + tni * SDT);

        out[(1 * NP + i) * 2 + 0] = nore;
        out[(1 * NP + i) * 2 + 1] = noim;
        out[(2 * NP + i) * 2 + 0] = oxv;
        out[(2 * NP + i) * 2 + 1] = oyv;
        out[(3 * NP + i) * 2 + 0] = lx;
        out[(3 * NP + i) * 2 + 1] = ly;
        out[(4 * NP + i) * 2 + 0] = rxx;
        out[(4 * NP + i) * 2 + 1] = ryy;
    }

    // publish translated positions for the sweep
    __syncthreads();
    #pragma unroll
    for (int s = 0; s < SEGS; s++)
        s_p[tid + s * NTHR] = make_float2(npx[s], npy[s]);
    __syncthreads();

    // ---- phase D: collision sweeps (smem-resident, early break) ----
    const float THR   = (float)(2.0 * 3.15e-6);     // 2*Rc
    const float THR2G = THR * THR * 1.0005f;
    const float MOVC  = (float)(2.1 * 3.15e-6);

    for (int t = 0; t < 30; t++) {
        float2 mv[SEGS];
        int mycoll = 0;
        #pragma unroll
        for (int s = 0; s < SEGS; s++) {
            int p = tid + s * NTHR;
            float2 pc = s_p[p];
            float mx = 0.f, my = 0.f;
            int cnt = myc[s];
            for (int k = 0; k < cnt; k++) {
                int j = s_nbr[k * NP + p];
                float2 q = s_p[j];
                float dx = q.x - pc.x, dy = q.y - pc.y;   // p_j - p_i
                float r2 = fmaf(dx, dx, dy * dy);
                if (r2 <= THR2G) {
                    float rinv = __frsqrt_rn(r2);
                    float absd = r2 * rinv;
                    if (absd <= THR) {
                        float f = (MOVC - absd) * 0.5f * rinv;
                        mx += dx * f;
                        my += dy * f;
                        mycoll = 1;
                    }
                }
            }
            mv[s] = make_float2(pc.x - mx, pc.y - my);
        }
        int any = __syncthreads_or(mycoll);   // barrier: all reads done + flag reduced
        #pragma unroll
        for (int s = 0; s < SEGS; s++) s_p[tid + s * NTHR] = mv[s];
        __syncthreads();                      // writes visible
        if (!any) break;                      // uniform decision
    }

    #pragma unroll
    for (int s = 0; s < SEGS; s++) {
        int p = tid + s * NTHR;
        out[p * 2 + 0] = s_p[p].x;
        out[p * 2 + 1] = s_p[p].y;
    }
}

// ---------------------------------------------------------------------------
extern "C" void kernel_launch(void* const* d_in, const int* in_sizes, int n_in,
                              void* d_out, int out_size) {
    const float* pre    = (const float*)d_in[0];
    const float* pim    = (const float*)d_in[1];
    const float* ore    = (const float*)d_in[2];
    const float* oim    = (const float*)d_in[3];
    const float* deltas = (const float*)d_in[4];
    const float* rnoise = (const float*)d_in[5];
    const float* tnre   = (const float*)d_in[6];
    const float* tnim   = (const float*)d_in[7];
    float* out = (float*)d_out;

    cudaFuncSetAttribute(fused_kernel, cudaFuncAttributeMaxDynamicSharedMemorySize, SMEM_BYTES);
    fused_kernel<<<1, NTHR, SMEM_BYTES>>>(pre, pim, ore, oim, deltas, rnoise,
                                          tnre, tnim, out);
}

// round 11
// speedup vs baseline: 14.8743x; 1.5538x over previous
#include <cuda_runtime.h>
#include <math.h>

#define NP    4096
#define NC    45       // cells per side
#define NCELL 2025
#define CPAD  2048
#define CAPT  12       // per-particle collision candidate cap

#define PI_F     3.1415927410125732f
#define TWOPI_F  6.2831854820251465f

// global scratch (no allocation allowed)
static __device__ float2         g_pos[NP];        // translated positions (K2 -> K3)
static __device__ unsigned short g_srt[NP];        // cell-sorted particle ids
static __device__ unsigned int   g_scan[CPAD];     // inclusive scan of cell counts
static __device__ unsigned short g_nbr[CAPT * NP]; // [k][i] collision candidates
static __device__ unsigned char  g_cnt[NP];
static __device__ float          g_cms[2];

#define INV_CELL ((float)NC / 1.28e-3f)

// ---------------------------------------------------------------------------
// K1: binning (histogram + scan + scatter) + deterministic cms.  1 block.
// ---------------------------------------------------------------------------
__global__ void __launch_bounds__(1024, 1)
bin_kernel(const float* __restrict__ pre, const float* __restrict__ pim) {
    __shared__ unsigned int   s_cnt[CPAD];
    __shared__ unsigned int   s_scan[CPAD];
    __shared__ unsigned short s_cell[NP];
    __shared__ unsigned short s_srt[NP];
    __shared__ float          s_red[2048];

    int tid = threadIdx.x;
    s_cnt[tid] = 0u; s_cnt[tid + 1024] = 0u;
    __syncthreads();

    float ax = 0.f, ay = 0.f;
    #pragma unroll
    for (int s = 0; s < 4; s++) {
        int k = tid + s * 1024;
        float px = pre[k], py = pim[k];
        int cx = (int)(px * INV_CELL); cx = cx < 0 ? 0 : (cx > NC - 1 ? NC - 1 : cx);
        int cy = (int)(py * INV_CELL); cy = cy < 0 ? 0 : (cy > NC - 1 ? NC - 1 : cy);
        int cell = cy * NC + cx;
        s_cell[k] = (unsigned short)cell;
        atomicAdd(&s_cnt[cell], 1u);
        ax += px; ay += py;
    }
    s_red[tid] = ax; s_red[1024 + tid] = ay;
    __syncthreads();
    for (int s = 512; s > 0; s >>= 1) {
        if (tid < s) { s_red[tid] += s_red[tid + s]; s_red[1024 + tid] += s_red[1024 + tid + s]; }
        __syncthreads();
    }
    if (tid == 0) {
        g_cms[0] = s_red[0] * (1.0f / NP);       // n_a = 4096 exactly
        g_cms[1] = s_red[1024] * (1.0f / NP);
    }

    // inclusive scan over 2048 (Hillis-Steele)
    s_scan[tid] = s_cnt[tid];
    s_scan[tid + 1024] = s_cnt[tid + 1024];
    __syncthreads();
    for (int off = 1; off < CPAD; off <<= 1) {
        unsigned v0 = (tid >= off) ? s_scan[tid - off] : 0u;
        unsigned v1 = s_scan[tid + 1024 - off];
        __syncthreads();
        s_scan[tid] += v0;
        s_scan[tid + 1024] += v1;
        __syncthreads();
    }
    // cursors = exclusive start
    {
        unsigned c0 = s_cnt[tid], c1 = s_cnt[tid + 1024];
        s_cnt[tid] = s_scan[tid] - c0;
        s_cnt[tid + 1024] = s_scan[tid + 1024] - c1;
    }
    __syncthreads();
    #pragma unroll
    for (int s = 0; s < 4; s++) {
        int k = tid + s * 1024;
        unsigned pos = atomicAdd(&s_cnt[s_cell[k]], 1u);
        s_srt[pos] = (unsigned short)k;
    }
    __syncthreads();

    // dump to global
    g_scan[tid] = s_scan[tid];
    g_scan[tid + 1024] = s_scan[tid + 1024];
    #pragma unroll
    for (int s = 0; s < 4; s++) {
        int k = tid + s * 1024;
        g_srt[k] = s_srt[k];
    }
}

// ---------------------------------------------------------------------------
// K2: neighborhood masks + per-particle epilogue.  16 blocks x 256 threads,
// one particle per thread; hot arrays staged in smem per block.
// smem: s_p f2[NP] 32KB | s_o f2[NP] 32KB | s_srt u16[NP] 8KB | s_scan u32 8KB
// ---------------------------------------------------------------------------
#define K2_SMEM (32768 + 32768 + 8192 + 8192)

__global__ void __launch_bounds__(256)
pair_kernel(const float* __restrict__ pre, const float* __restrict__ pim,
            const float* __restrict__ ore, const float* __restrict__ oim,
            const float* __restrict__ deltas, const float* __restrict__ rnoise,
            const float* __restrict__ tnre, const float* __restrict__ tnim,
            float* __restrict__ out) {
    extern __shared__ char smem[];
    float2*         s_p    = (float2*)smem;
    float2*         s_o    = (float2*)(smem + 32768);
    unsigned short* s_srt  = (unsigned short*)(smem + 65536);
    unsigned int*   s_scan = (unsigned int*)(smem + 73728);

    int tid = threadIdx.x;
    for (int k = tid; k < NP; k += 256) {
        s_p[k] = make_float2(pre[k], pim[k]);
        s_o[k] = make_float2(ore[k], oim[k]);
        s_srt[k] = g_srt[k];
    }
    for (int k = tid; k < CPAD; k += 256) s_scan[k] = g_scan[k];
    __syncthreads();

    const float ROCf  = (float)(2.5e-5 + 3.15e-6);   // RO + RC = 28.15um
    const float ROC2G = ROCf * ROCf * 1.0005f;       // squared prefilter w/ guard
    const float RRf   = (float)(8e-6);
    const float RCAP  = (float)(4.5 * 3.15e-6);      // collision capture radius
    const float RCAP2 = RCAP * RCAP;

    int i = blockIdx.x * 256 + tid;
    float pxi = s_p[i].x, pyi = s_p[i].y;
    float orr = s_o[i].x, ori = s_o[i].y;

    int cx = (int)(pxi * INV_CELL); cx = cx < 0 ? 0 : (cx > NC - 1 ? NC - 1 : cx);
    int cy = (int)(pyi * INV_CELL); cy = cy < 0 ? 0 : (cy > NC - 1 ? NC - 1 : cy);
    int x0 = cx > 0 ? cx - 1 : 0, x1 = cx < NC - 1 ? cx + 1 : NC - 1;
    int y0 = cy > 0 ? cy - 1 : 0, y1 = cy < NC - 1 ? cy + 1 : NC - 1;

    float nr = 0.f, sxv = 0.f, syv = 0.f, oxv = 0.f, oyv = 0.f;
    int cc = 0;

    for (int gy = y0; gy <= y1; gy++) {
        int c0 = gy * NC + x0;
        int c1 = gy * NC + x1;
        int b = (c0 == 0) ? 0 : (int)s_scan[c0 - 1];
        int e = (int)s_scan[c1];
        for (int k = b; k < e; k++) {
            int j = s_srt[k];
            float2 pj = s_p[j];
            float dx = pxi - pj.x, dy = pyi - pj.y;
            float r2 = fmaf(dx, dx, dy * dy);
            bool same = (j == i);
            if (r2 <= ROC2G || same) {
                if (r2 <= RCAP2 && !same) {                 // collision candidate
                    if (cc < CAPT) g_nbr[cc * NP + i] = (unsigned short)j;
                    cc++;
                }
                float dist = same ? 1.0f : __fsqrt_rn(r2);  // diag dist = 1 (eye)
                float2 oj = s_o[j];
                if (dist <= ROCf || same) {                 // mask_ro (self incl.)
                    oxv += oj.x;
                    oyv += oj.y;
                }
                if (dist <= RRf && !same) {                 // mask_rr (self excl.)
                    // in_front: |wrap(ang_i - ang_j)| < pi/2  <=>  ori_i . ori_j > 0
                    if (fmaf(orr, oj.x, ori * oj.y) > 0.f) {
                        nr += 1.0f; sxv += pj.x; syv += pj.y;
                    }
                }
            }
        }
    }
    g_cnt[i] = (unsigned char)(cc > CAPT ? CAPT : cc);

    // ---- epilogue ----
    float sgn = (nr > 0.f) ? 1.f : 0.f;
    float den = fmaxf(nr, 1.f);
    float SSx = sxv / den - pxi * sgn;
    float SSy = syv / den - pyi * sgn;
    float ddx = -SSx, ddy = -SSy;

    float Px = g_cms[0] - pxi;               // Ps = cms - pos (Ra = inf)
    float Py = g_cms[1] - pyi;

    float del = deltas[i];
    float cd = cosf(del), sd = sinf(del);
    float lx = Px * cd - Py * sd;            // Ps * e^{+i delta}
    float ly = Px * sd + Py * cd;
    float rxx = Px * cd + Py * sd;           // Ps * e^{-i delta}
    float ryy = Py * cd - Px * sd;

    float dl = lx * oxv + ly * oyv;
    float dr = rxx * oxv + ryy * oyv;
    float no = fmaxf(__fsqrt_rn(oxv * oxv + oyv * oyv), 1e-14f);
    float cl = dl / (fmaxf(__fsqrt_rn(lx * lx + ly * ly), 1e-14f) * no);
    float cr = dr / (fmaxf(__fsqrt_rn(rxx * rxx + ryy * ryy), 1e-14f) * no);
    bool usel = (cl >= cr);
    float bx = usel ? lx : rxx;
    float by = usel ? ly : ryy;

    bool hasrep = (ddx != 0.f) || (ddy != 0.f);
    float tx = hasrep ? ddx : bx;
    float ty = hasrep ? ddy : by;
    float att = atan2f(ty, tx) - atan2f(ori, orr);
    if (att <= -PI_F) { float r = fmodf(att, PI_F); if (r < 0.f) r += PI_F; att = r; }
    if (att >= PI_F) att -= TWOPI_F;

    const float CTH  = (float)(0.2 * 25.0 * 0.0028);         // DT*GAMMA*DR
    const float S2DR = (float)0.07483314773547883;           // sqrt(2*DR)
    const float SDT  = (float)0.4472135954999579;            // sqrt(DT)
    float theta = CTH * sinf(att) + rnoise[i] * S2DR * SDT;
    float rc = cosf(theta), rs = sinf(theta);
    float nore = orr * rc - ori * rs;
    float noim = orr * rs + ori * rc;

    const float CH    = (float)0.7071067811865476;           // sqrt(0.5)
    const float CTT   = (float)1.6733200530681511e-7;        // sqrt(2*DT_TRANS)
    const float DTVEL = (float)(0.2 * 5e-7);                 // DT*VEL
    float tnr = tnre[i] * CH * CTT;
    float tni = tnim[i] * CH * CTT;
    g_pos[i] = make_float2(pxi + (DTVEL * orr + tnr * SDT),
                           pyi + (DTVEL * ori + tni * SDT));

    out[(1 * NP + i) * 2 + 0] = nore;
    out[(1 * NP + i) * 2 + 1] = noim;
    out[(2 * NP + i) * 2 + 0] = oxv;
    out[(2 * NP + i) * 2 + 1] = oyv;
    out[(3 * NP + i) * 2 + 0] = lx;
    out[(3 * NP + i) * 2 + 1] = ly;
    out[(4 * NP + i) * 2 + 0] = rxx;
    out[(4 * NP + i) * 2 + 1] = ryy;
}

// ---------------------------------------------------------------------------
// K3: collision sweeps.  1 block, smem-resident, early break (ref `cont`).
// smem: s_pos f2[NP] 32KB | s_nbr u16[CAPT*NP] 96KB
// ---------------------------------------------------------------------------
#define K3_SMEM (32768 + 98304)

__global__ void __launch_bounds__(1024, 1)
sweep_kernel(float* __restrict__ out) {
    extern __shared__ char smem[];
    float2*         s_pos = (float2*)smem;
    unsigned short* s_nbr = (unsigned short*)(smem + 32768);

    int tid = threadIdx.x;
    #pragma unroll
    for (int s = 0; s < 4; s++) {
        int k = tid + s * 1024;
        s_pos[k] = g_pos[k];
    }
    for (int k = tid; k < CAPT * NP; k += 1024) s_nbr[k] = g_nbr[k];
    int myc[4];
    #pragma unroll
    for (int s = 0; s < 4; s++) myc[s] = g_cnt[tid + s * 1024];
    __syncthreads();

    const float THR   = (float)(2.0 * 3.15e-6);     // 2*Rc
    const float THR2G = THR * THR * 1.0005f;
    const float MOVC  = (float)(2.1 * 3.15e-6);

    for (int t = 0; t < 30; t++) {
        float2 mv[4];
        int mycoll = 0;
        #pragma unroll
        for (int s = 0; s < 4; s++) {
            int p = tid + s * 1024;
            float2 pc = s_pos[p];
            float mx = 0.f, my = 0.f;
            int cnt = myc[s];
            for (int k = 0; k < cnt; k++) {
                int j = s_nbr[k * NP + p];
                float2 q = s_pos[j];
                float dx = q.x - pc.x, dy = q.y - pc.y;   // p_j - p_i
                float r2 = fmaf(dx, dx, dy * dy);
                if (r2 <= THR2G) {
                    float rinv = __frsqrt_rn(r2);
                    float absd = r2 * rinv;
                    if (absd <= THR) {
                        float f = (MOVC - absd) * 0.5f * rinv;
                        mx += dx * f;
                        my += dy * f;
                        mycoll = 1;
                    }
                }
            }
            mv[s] = make_float2(pc.x - mx, pc.y - my);
        }
        int any = __syncthreads_or(mycoll);   // barrier: reads done + flag reduced
        #pragma unroll
        for (int s = 0; s < 4; s++) s_pos[tid + s * 1024] = mv[s];
        __syncthreads();                      // writes visible
        if (!any) break;                      // uniform decision
    }

    #pragma unroll
    for (int s = 0; s < 4; s++) {
        int p = tid + s * 1024;
        out[p * 2 + 0] = s_pos[p].x;
        out[p * 2 + 1] = s_pos[p].y;
    }
}

// ---------------------------------------------------------------------------
extern "C" void kernel_launch(void* const* d_in, const int* in_sizes, int n_in,
                              void* d_out, int out_size) {
    const float* pre    = (const float*)d_in[0];
    const float* pim    = (const float*)d_in[1];
    const float* ore    = (const float*)d_in[2];
    const float* oim    = (const float*)d_in[3];
    const float* deltas = (const float*)d_in[4];
    const float* rnoise = (const float*)d_in[5];
    const float* tnre   = (const float*)d_in[6];
    const float* tnim   = (const float*)d_in[7];
    float* out = (float*)d_out;

    bin_kernel<<<1, 1024>>>(pre, pim);

    cudaFuncSetAttribute(pair_kernel, cudaFuncAttributeMaxDynamicSharedMemorySize, K2_SMEM);
    pair_kernel<<<16, 256, K2_SMEM>>>(pre, pim, ore, oim, deltas, rnoise, tnre, tnim, out);

    cudaFuncSetAttribute(sweep_kernel, cudaFuncAttributeMaxDynamicSharedMemorySize, K3_SMEM);
    sweep_kernel<<<1, 1024, K3_SMEM>>>(out);
}

// round 12
// speedup vs baseline: 18.2130x; 1.2245x over previous
#include <cuda_runtime.h>
#include <math.h>

#define NP    4096
#define NC    45       // cells per side
#define NCELL 2025
#define CPAD  2048
#define CAPT  12       // per-particle collision candidate cap
#define K2B   16       // pair-kernel blocks
#define K2T   256      // pair-kernel threads/block

#define PI_F     3.1415927410125732f
#define TWOPI_F  6.2831854820251465f

// global scratch (no allocation allowed)
static __device__ float2         g_pos[NP];        // translated positions (A -> B)
static __device__ unsigned short g_nbr[CAPT * NP]; // [k][i] collision candidates (raw ids)
static __device__ unsigned char  g_cnt[NP];

#define INV_CELL ((float)NC / 1.28e-3f)

// ---------------------------------------------------------------------------
// Kernel A: per-block binning + neighborhood masks + per-particle epilogue.
// 16 blocks x 256 threads; each block redundantly builds the cell index in
// its own smem (parallel in time), then handles its 256 particles.
// smem: s_p f2[NP] 32KB | s_o f2[NP] 32KB | s_cnt u32[CPAD] 8KB |
//       s_scan u32[CPAD] 8KB | s_cell u16[NP] 8KB | s_srt u16[NP] 8KB
// ---------------------------------------------------------------------------
#define KA_SMEM (32768 + 32768 + 8192 + 8192 + 8192 + 8192)   // 98304

__global__ void __launch_bounds__(K2T)
pair_kernel(const float* __restrict__ pre, const float* __restrict__ pim,
            const float* __restrict__ ore, const float* __restrict__ oim,
            const float* __restrict__ deltas, const float* __restrict__ rnoise,
            const float* __restrict__ tnre, const float* __restrict__ tnim,
            float* __restrict__ out) {
    extern __shared__ char smem[];
    float2*         s_p    = (float2*)smem;
    float2*         s_o    = (float2*)(smem + 32768);
    unsigned int*   s_cnt  = (unsigned int*)(smem + 65536);
    unsigned int*   s_scan = (unsigned int*)(smem + 73728);
    unsigned short* s_cell = (unsigned short*)(smem + 81920);
    unsigned short* s_srt  = (unsigned short*)(smem + 90112);
    __shared__ float s_ws[64];      // warp partial sums / scan temporaries
    __shared__ float s_cms[2];

    int tid = threadIdx.x;
    int lane = tid & 31, wrp = tid >> 5;    // 8 warps

    // ---- load + histogram + cms partials ----
    #pragma unroll
    for (int s = 0; s < 8; s++) s_cnt[tid + s * K2T] = 0u;
    __syncthreads();

    float ax = 0.f, ay = 0.f;
    #pragma unroll
    for (int s = 0; s < 16; s++) {
        int k = tid + s * K2T;              // deterministic fixed order per thread
        float px = pre[k], py = pim[k];
        s_p[k] = make_float2(px, py);
        s_o[k] = make_float2(ore[k], oim[k]);
        int cx = (int)(px * INV_CELL); cx = cx < 0 ? 0 : (cx > NC - 1 ? NC - 1 : cx);
        int cy = (int)(py * INV_CELL); cy = cy < 0 ? 0 : (cy > NC - 1 ? NC - 1 : cy);
        int cell = cy * NC + cx;
        s_cell[k] = (unsigned short)cell;
        atomicAdd(&s_cnt[cell], 1u);
        ax += px; ay += py;
    }
    // shfl reduction (fixed order -> deterministic, identical in every block)
    #pragma unroll
    for (int o = 16; o > 0; o >>= 1) {
        ax += __shfl_down_sync(0xffffffffu, ax, o);
        ay += __shfl_down_sync(0xffffffffu, ay, o);
    }
    if (lane == 0) { s_ws[wrp] = ax; s_ws[8 + wrp] = ay; }
    __syncthreads();
    if (tid == 0) {
        float sx = 0.f, sy = 0.f;
        #pragma unroll
        for (int w = 0; w < 8; w++) { sx += s_ws[w]; sy += s_ws[8 + w]; }
        s_cms[0] = sx * (1.0f / NP);        // n_a = 4096 exactly
        s_cms[1] = sy * (1.0f / NP);
    }
    __syncthreads();

    // ---- inclusive scan over CPAD=2048 cells: 8 cells/thread + warp shfl ----
    {
        unsigned v[8]; unsigned run = 0u;
        int base = tid * 8;
        #pragma unroll
        for (int q = 0; q < 8; q++) { run += s_cnt[base + q]; v[q] = run; }
        unsigned tot = run;
        // warp inclusive scan of tot
        #pragma unroll
        for (int o = 1; o < 32; o <<= 1) {
            unsigned n = __shfl_up_sync(0xffffffffu, tot, o);
            if (lane >= o) tot += n;
        }
        if (lane == 31) ((unsigned*)s_ws)[wrp] = tot;   // warp total (inclusive)
        unsigned lanepre = tot - run;                   // exclusive prefix within warp
        __syncthreads();
        unsigned wpre = 0u;
        #pragma unroll
        for (int w = 0; w < 8; w++) { unsigned t = ((unsigned*)s_ws)[w]; if (w < wrp) wpre += t; }
        unsigned off = wpre + lanepre;
        #pragma unroll
        for (int q = 0; q < 8; q++) s_scan[base + q] = v[q] + off;
    }
    __syncthreads();

    // ---- scatter: cursor = exclusive start ----
    {
        #pragma unroll
        for (int s = 0; s < 8; s++) {
            int c = tid + s * K2T;
            s_cnt[c] = s_scan[c] - s_cnt[c];
        }
    }
    __syncthreads();
    #pragma unroll
    for (int s = 0; s < 16; s++) {
        int k = tid + s * K2T;
        unsigned pos = atomicAdd(&s_cnt[s_cell[k]], 1u);
        s_srt[pos] = (unsigned short)k;
    }
    __syncthreads();

    // ---- neighborhood scan for this block's 256 particles ----
    const float ROCf  = (float)(2.5e-5 + 3.15e-6);   // RO + RC = 28.15um
    const float ROC2G = ROCf * ROCf * 1.0005f;       // squared prefilter w/ guard
    const float RRf   = (float)(8e-6);
    const float RCAP  = (float)(4.5 * 3.15e-6);      // collision capture radius
    const float RCAP2 = RCAP * RCAP;

    int i = blockIdx.x * K2T + tid;
    float pxi = s_p[i].x, pyi = s_p[i].y;
    float orr = s_o[i].x, ori = s_o[i].y;

    int cell = s_cell[i];
    int cx = cell % NC, cy = cell / NC;
    int x0 = cx > 0 ? cx - 1 : 0, x1 = cx < NC - 1 ? cx + 1 : NC - 1;
    int y0 = cy > 0 ? cy - 1 : 0, y1 = cy < NC - 1 ? cy + 1 : NC - 1;

    float nr = 0.f, sxv = 0.f, syv = 0.f, oxv = 0.f, oyv = 0.f;
    int cc = 0;

    for (int gy = y0; gy <= y1; gy++) {
        int c0 = gy * NC + x0;
        int c1 = gy * NC + x1;
        int b = (c0 == 0) ? 0 : (int)s_scan[c0 - 1];
        int e = (int)s_scan[c1];
        for (int k = b; k < e; k++) {
            int j = s_srt[k];
            float2 pj = s_p[j];
            float dx = pxi - pj.x, dy = pyi - pj.y;
            float r2 = fmaf(dx, dx, dy * dy);
            bool same = (j == i);
            if (r2 <= ROC2G || same) {
                if (r2 <= RCAP2 && !same) {                 // collision candidate
                    if (cc < CAPT) g_nbr[cc * NP + i] = (unsigned short)j;
                    cc++;
                }
                float dist = same ? 1.0f : __fsqrt_rn(r2);  // diag dist = 1 (eye)
                float2 oj = s_o[j];
                if (dist <= ROCf || same) {                 // mask_ro (self incl.)
                    oxv += oj.x;
                    oyv += oj.y;
                }
                if (dist <= RRf && !same) {                 // mask_rr (self excl.)
                    // in_front: |wrap(ang_i - ang_j)| < pi/2  <=>  ori_i . ori_j > 0
                    if (fmaf(orr, oj.x, ori * oj.y) > 0.f) {
                        nr += 1.0f; sxv += pj.x; syv += pj.y;
                    }
                }
            }
        }
    }
    g_cnt[i] = (unsigned char)(cc > CAPT ? CAPT : cc);

    // ---- epilogue ----
    float sgn = (nr > 0.f) ? 1.f : 0.f;
    float den = fmaxf(nr, 1.f);
    float SSx = sxv / den - pxi * sgn;
    float SSy = syv / den - pyi * sgn;
    float ddx = -SSx, ddy = -SSy;

    float Px = s_cms[0] - pxi;               // Ps = cms - pos (Ra = inf)
    float Py = s_cms[1] - pyi;

    float del = deltas[i];
    float cd = cosf(del), sd = sinf(del);
    float lx = Px * cd - Py * sd;            // Ps * e^{+i delta}
    float ly = Px * sd + Py * cd;
    float rxx = Px * cd + Py * sd;           // Ps * e^{-i delta}
    float ryy = Py * cd - Px * sd;

    float dl = lx * oxv + ly * oyv;
    float dr = rxx * oxv + ryy * oyv;
    float no = fmaxf(__fsqrt_rn(oxv * oxv + oyv * oyv), 1e-14f);
    float cl = dl / (fmaxf(__fsqrt_rn(lx * lx + ly * ly), 1e-14f) * no);
    float cr = dr / (fmaxf(__fsqrt_rn(rxx * rxx + ryy * ryy), 1e-14f) * no);
    bool usel = (cl >= cr);
    float bx = usel ? lx : rxx;
    float by = usel ? ly : ryy;

    bool hasrep = (ddx != 0.f) || (ddy != 0.f);
    float tx = hasrep ? ddx : bx;
    float ty = hasrep ? ddy : by;
    float att = atan2f(ty, tx) - atan2f(ori, orr);
    if (att <= -PI_F) { float r = fmodf(att, PI_F); if (r < 0.f) r += PI_F; att = r; }
    if (att >= PI_F) att -= TWOPI_F;

    const float CTH  = (float)(0.2 * 25.0 * 0.0028);         // DT*GAMMA*DR
    const float S2DR = (float)0.07483314773547883;           // sqrt(2*DR)
    const float SDT  = (float)0.4472135954999579;            // sqrt(DT)
    float theta = CTH * sinf(att) + rnoise[i] * S2DR * SDT;
    float rc = cosf(theta), rs = sinf(theta);
    float nore = orr * rc - ori * rs;
    float noim = orr * rs + ori * rc;

    const float CH    = (float)0.7071067811865476;           // sqrt(0.5)
    const float CTT   = (float)1.6733200530681511e-7;        // sqrt(2*DT_TRANS)
    const float DTVEL = (float)(0.2 * 5e-7);                 // DT*VEL
    float tnr = tnre[i] * CH * CTT;
    float tni = tnim[i] * CH * CTT;
    g_pos[i] = make_float2(pxi + (DTVEL * orr + tnr * SDT),
                           pyi + (DTVEL * ori + tni * SDT));

    out[(1 * NP + i) * 2 + 0] = nore;
    out[(1 * NP + i) * 2 + 1] = noim;
    out[(2 * NP + i) * 2 + 0] = oxv;
    out[(2 * NP + i) * 2 + 1] = oyv;
    out[(3 * NP + i) * 2 + 0] = lx;
    out[(3 * NP + i) * 2 + 1] = ly;
    out[(4 * NP + i) * 2 + 0] = rxx;
    out[(4 * NP + i) * 2 + 1] = ryy;
}

// ---------------------------------------------------------------------------
// Kernel B: collision sweeps. 1 block, smem ping-pong, ONE barrier per
// iteration, early break (matches reference `cont`).
// smem: P0 f2[NP] 32KB | P1 f2[NP] 32KB | s_nbr u16[CAPT*NP] 96KB
// ---------------------------------------------------------------------------
#define KB_SMEM (32768 + 32768 + 98304)   // 163840

__global__ void __launch_bounds__(1024, 1)
sweep_kernel(float* __restrict__ out) {
    extern __shared__ char smem[];
    float2*         P0    = (float2*)smem;
    float2*         P1    = (float2*)(smem + 32768);
    unsigned short* s_nbr = (unsigned short*)(smem + 65536);

    int tid = threadIdx.x;
    #pragma unroll
    for (int s = 0; s < 4; s++) {
        int k = tid + s * 1024;
        P0[k] = g_pos[k];
    }
    {
        const uint4* src = (const uint4*)g_nbr;   // 96KB = 6144 uint4
        uint4* dst = (uint4*)s_nbr;
        #pragma unroll
        for (int s = 0; s < 6; s++) dst[tid + s * 1024] = src[tid + s * 1024];
    }
    int myc[4];
    #pragma unroll
    for (int s = 0; s < 4; s++) myc[s] = g_cnt[tid + s * 1024];
    __syncthreads();

    const float THR   = (float)(2.0 * 3.15e-6);     // 2*Rc
    const float THR2G = THR * THR * 1.0005f;
    const float MOVC  = (float)(2.1 * 3.15e-6);

    float2* C = P0;
    float2* N = P1;
    for (int t = 0; t < 30; t++) {
        int mycoll = 0;
        #pragma unroll
        for (int s = 0; s < 4; s++) {
            int p = tid + s * 1024;
            float2 pc = C[p];
            float mx = 0.f, my = 0.f;
            int cnt = myc[s];
            for (int k = 0; k < cnt; k++) {
                int j = s_nbr[k * NP + p];
                float2 q = C[j];
                float dx = q.x - pc.x, dy = q.y - pc.y;   // p_j - p_i
                float r2 = fmaf(dx, dx, dy * dy);
                if (r2 <= THR2G) {
                    float rinv = __frsqrt_rn(r2);
                    float absd = r2 * rinv;
                    if (absd <= THR) {
                        float f = (MOVC - absd) * 0.5f * rinv;
                        mx += dx * f;
                        my += dy * f;
                        mycoll = 1;
                    }
                }
            }
            N[p] = make_float2(pc.x - mx, pc.y - my);   // write to OTHER buffer
        }
        int any = __syncthreads_or(mycoll);   // single barrier: N writes visible + flag
        float2* tmp = C; C = N; N = tmp;      // next iter reads what we just wrote
        if (!any) break;                      // uniform decision
    }

    #pragma unroll
    for (int s = 0; s < 4; s++) {
        int p = tid + s * 1024;
        out[p * 2 + 0] = C[p].x;
        out[p * 2 + 1] = C[p].y;
    }
}

// ---------------------------------------------------------------------------
extern "C" void kernel_launch(void* const* d_in, const int* in_sizes, int n_in,
                              void* d_out, int out_size) {
    const float* pre    = (const float*)d_in[0];
    const float* pim    = (const float*)d_in[1];
    const float* ore    = (const float*)d_in[2];
    const float* oim    = (const float*)d_in[3];
    const float* deltas = (const float*)d_in[4];
    const float* rnoise = (const float*)d_in[5];
    const float* tnre   = (const float*)d_in[6];
    const float* tnim   = (const float*)d_in[7];
    float* out = (float*)d_out;

    cudaFuncSetAttribute(pair_kernel, cudaFuncAttributeMaxDynamicSharedMemorySize, KA_SMEM);
    pair_kernel<<<K2B, K2T, KA_SMEM>>>(pre, pim, ore, oim, deltas, rnoise, tnre, tnim, out);

    cudaFuncSetAttribute(sweep_kernel, cudaFuncAttributeMaxDynamicSharedMemorySize, KB_SMEM);
    sweep_kernel<<<1, 1024, KB_SMEM>>>(out);
}

// round 13
// speedup vs baseline: 19.9272x; 1.0941x over previous
#include <cuda_runtime.h>
#include <math.h>

#define NP    4096
#define NC    45       // cells per side
#define NCELL 2025
#define CPAD  2048
#define CAPT  12       // per-particle collision candidate cap
#define NBLK  8
#define NTHR  512
#define PPT   8        // NP / NTHR

#define PI_F     3.1415927410125732f
#define TWOPI_F  6.2831854820251465f

// global scratch (no allocation allowed)
static __device__ float2         g_pos[NP];        // translated positions
static __device__ unsigned short g_nbr[CAPT * NP]; // [k][i] collision candidates
static __device__ unsigned char  g_cnt[NP];
static __device__ int            g_done;           // zero-init; reset by sweep block

#define INV_CELL ((float)NC / 1.28e-3f)

// smem union (bytes):
//  pair view : s_p f2[NP] 32K | s_o f2[NP] 32K | s_hc u32[CPAD] 8K |
//              s_scan u32[CPAD] 8K | s_cell u16[NP] 8K | s_srt u16[NP] 8K = 96K
//  sweep view: P0 f2[NP] 32K | P1 f2[NP] 32K | s_nbr u16[CAPT*NP] 96K |
//              s_perm u16[NP] 8K | s_ca u8[NP] 4K = 172K
#define SMEM_BYTES 176128

__global__ void __launch_bounds__(NTHR, 1)
fused_kernel(const float* __restrict__ pre, const float* __restrict__ pim,
             const float* __restrict__ ore, const float* __restrict__ oim,
             const float* __restrict__ deltas, const float* __restrict__ rnoise,
             const float* __restrict__ tnre, const float* __restrict__ tnim,
             float* __restrict__ out) {
    extern __shared__ char smem[];
    // pair view
    float2*         s_p    = (float2*)smem;
    float2*         s_o    = (float2*)(smem + 32768);
    unsigned int*   s_hc   = (unsigned int*)(smem + 65536);
    unsigned int*   s_scan = (unsigned int*)(smem + 73728);
    unsigned short* s_cell = (unsigned short*)(smem + 81920);
    unsigned short* s_srt  = (unsigned short*)(smem + 90112);

    __shared__ float s_ws[32];
    __shared__ float s_cms[2];
    __shared__ int   s_last;
    __shared__ unsigned s_hist[16];

    int tid = threadIdx.x;
    int lane = tid & 31, wrp = tid >> 5;    // 16 warps

    // ---- pair phase A: load + histogram + cms ----
    #pragma unroll
    for (int s = 0; s < 4; s++) s_hc[tid + s * NTHR] = 0u;
    __syncthreads();

    float ax = 0.f, ay = 0.f;
    #pragma unroll
    for (int s = 0; s < PPT; s++) {
        int k = tid + s * NTHR;
        float px = pre[k], py = pim[k];
        s_p[k] = make_float2(px, py);
        s_o[k] = make_float2(ore[k], oim[k]);
        int cx = (int)(px * INV_CELL); cx = cx < 0 ? 0 : (cx > NC - 1 ? NC - 1 : cx);
        int cy = (int)(py * INV_CELL); cy = cy < 0 ? 0 : (cy > NC - 1 ? NC - 1 : cy);
        int cell = cy * NC + cx;
        s_cell[k] = (unsigned short)cell;
        atomicAdd(&s_hc[cell], 1u);
        ax += px; ay += py;
    }
    #pragma unroll
    for (int o = 16; o > 0; o >>= 1) {
        ax += __shfl_down_sync(0xffffffffu, ax, o);
        ay += __shfl_down_sync(0xffffffffu, ay, o);
    }
    if (lane == 0) { s_ws[wrp] = ax; s_ws[16 + wrp] = ay; }
    __syncthreads();
    if (tid == 0) {
        float sx = 0.f, sy = 0.f;
        #pragma unroll
        for (int w = 0; w < 16; w++) { sx += s_ws[w]; sy += s_ws[16 + w]; }
        s_cms[0] = sx * (1.0f / NP);        // n_a = 4096 exactly
        s_cms[1] = sy * (1.0f / NP);
    }
    __syncthreads();

    // ---- inclusive scan over 2048 cells: 4 cells/thread + warp shfl ----
    {
        unsigned v[4]; unsigned run = 0u;
        int base = tid * 4;
        #pragma unroll
        for (int q = 0; q < 4; q++) { run += s_hc[base + q]; v[q] = run; }
        unsigned tot = run;
        #pragma unroll
        for (int o = 1; o < 32; o <<= 1) {
            unsigned n = __shfl_up_sync(0xffffffffu, tot, o);
            if (lane >= o) tot += n;
        }
        if (lane == 31) ((unsigned*)s_ws)[wrp] = tot;
        unsigned lanepre = tot - run;
        __syncthreads();
        unsigned wpre = 0u;
        #pragma unroll
        for (int w = 0; w < 16; w++) { unsigned t = ((unsigned*)s_ws)[w]; if (w < wrp) wpre += t; }
        unsigned off = wpre + lanepre;
        #pragma unroll
        for (int q = 0; q < 4; q++) s_scan[base + q] = v[q] + off;
    }
    __syncthreads();
    #pragma unroll
    for (int s = 0; s < 4; s++) {
        int c = tid + s * NTHR;
        s_hc[c] = s_scan[c] - s_hc[c];      // cursor = exclusive start
    }
    __syncthreads();
    #pragma unroll
    for (int s = 0; s < PPT; s++) {
        int k = tid + s * NTHR;
        unsigned pos = atomicAdd(&s_hc[s_cell[k]], 1u);
        s_srt[pos] = (unsigned short)k;
    }
    __syncthreads();

    // ---- pair phase B: neighborhood scan for this block's 512 particles ----
    const float ROCf  = (float)(2.5e-5 + 3.15e-6);   // RO + RC = 28.15um
    const float ROC2G = ROCf * ROCf * 1.0005f;
    const float RRf   = (float)(8e-6);
    const float RCAP  = (float)(4.5 * 3.15e-6);
    const float RCAP2 = RCAP * RCAP;

    int i = blockIdx.x * NTHR + tid;
    float pxi = s_p[i].x, pyi = s_p[i].y;
    float orr = s_o[i].x, ori = s_o[i].y;

    int cell = s_cell[i];
    int cx = cell % NC, cy = cell / NC;
    int x0 = cx > 0 ? cx - 1 : 0, x1 = cx < NC - 1 ? cx + 1 : NC - 1;
    int y0 = cy > 0 ? cy - 1 : 0, y1 = cy < NC - 1 ? cy + 1 : NC - 1;

    float nr = 0.f, sxv = 0.f, syv = 0.f, oxv = 0.f, oyv = 0.f;
    int cc = 0;

    for (int gy = y0; gy <= y1; gy++) {
        int c0 = gy * NC + x0;
        int c1 = gy * NC + x1;
        int b = (c0 == 0) ? 0 : (int)s_scan[c0 - 1];
        int e = (int)s_scan[c1];
        for (int k = b; k < e; k++) {
            int j = s_srt[k];
            float2 pj = s_p[j];
            float dx = pxi - pj.x, dy = pyi - pj.y;
            float r2 = fmaf(dx, dx, dy * dy);
            bool same = (j == i);
            if (r2 <= ROC2G || same) {
                if (r2 <= RCAP2 && !same) {                 // collision candidate
                    if (cc < CAPT) g_nbr[cc * NP + i] = (unsigned short)j;
                    cc++;
                }
                float dist = same ? 1.0f : __fsqrt_rn(r2);  // diag dist = 1 (eye)
                float2 oj = s_o[j];
                if (dist <= ROCf || same) {                 // mask_ro (self incl.)
                    oxv += oj.x;
                    oyv += oj.y;
                }
                if (dist <= RRf && !same) {                 // mask_rr (self excl.)
                    // in_front: |wrap(ang_i - ang_j)| < pi/2 <=> ori_i . ori_j > 0
                    if (fmaf(orr, oj.x, ori * oj.y) > 0.f) {
                        nr += 1.0f; sxv += pj.x; syv += pj.y;
                    }
                }
            }
        }
    }
    g_cnt[i] = (unsigned char)(cc > CAPT ? CAPT : cc);

    // ---- epilogue ----
    float sgn = (nr > 0.f) ? 1.f : 0.f;
    float den = fmaxf(nr, 1.f);
    float SSx = sxv / den - pxi * sgn;
    float SSy = syv / den - pyi * sgn;
    float ddx = -SSx, ddy = -SSy;

    float Px = s_cms[0] - pxi;               // Ps = cms - pos (Ra = inf)
    float Py = s_cms[1] - pyi;

    float del = deltas[i];
    float cd = cosf(del), sd = sinf(del);
    float lx = Px * cd - Py * sd;
    float ly = Px * sd + Py * cd;
    float rxx = Px * cd + Py * sd;
    float ryy = Py * cd - Px * sd;

    float dl = lx * oxv + ly * oyv;
    float dr = rxx * oxv + ryy * oyv;
    float no = fmaxf(__fsqrt_rn(oxv * oxv + oyv * oyv), 1e-14f);
    float cl = dl / (fmaxf(__fsqrt_rn(lx * lx + ly * ly), 1e-14f) * no);
    float cr = dr / (fmaxf(__fsqrt_rn(rxx * rxx + ryy * ryy), 1e-14f) * no);
    bool usel = (cl >= cr);
    float bx = usel ? lx : rxx;
    float by = usel ? ly : ryy;

    bool hasrep = (ddx != 0.f) || (ddy != 0.f);
    float tx = hasrep ? ddx : bx;
    float ty = hasrep ? ddy : by;
    float att = atan2f(ty, tx) - atan2f(ori, orr);
    if (att <= -PI_F) { float r = fmodf(att, PI_F); if (r < 0.f) r += PI_F; att = r; }
    if (att >= PI_F) att -= TWOPI_F;

    const float CTH  = (float)(0.2 * 25.0 * 0.0028);
    const float S2DR = (float)0.07483314773547883;
    const float SDT  = (float)0.4472135954999579;
    float theta = CTH * sinf(att) + rnoise[i] * S2DR * SDT;
    float rc = cosf(theta), rs = sinf(theta);
    float nore = orr * rc - ori * rs;
    float noim = orr * rs + ori * rc;

    const float CH    = (float)0.7071067811865476;
    const float CTT   = (float)1.6733200530681511e-7;
    const float DTVEL = (float)(0.2 * 5e-7);
    float tnr = tnre[i] * CH * CTT;
    float tni = tnim[i] * CH * CTT;
    g_pos[i] = make_float2(pxi + (DTVEL * orr + tnr * SDT),
                           pyi + (DTVEL * ori + tni * SDT));

    out[(1 * NP + i) * 2 + 0] = nore;
    out[(1 * NP + i) * 2 + 1] = noim;
    out[(2 * NP + i) * 2 + 0] = oxv;
    out[(2 * NP + i) * 2 + 1] = oyv;
    out[(3 * NP + i) * 2 + 0] = lx;
    out[(3 * NP + i) * 2 + 1] = ly;
    out[(4 * NP + i) * 2 + 0] = rxx;
    out[(4 * NP + i) * 2 + 1] = ryy;

    // ---- last-block ticket ----
    __syncthreads();
    if (tid == 0) {
        __threadfence();
        int v = atomicAdd(&g_done, 1);
        s_last = (v == NBLK - 1) ? 1 : 0;
    }
    __syncthreads();
    if (!s_last) return;
    __threadfence();   // acquire all blocks' g_pos / g_nbr / g_cnt writes

    // ---- sweep phase (last block), cnt-sorted assignment ----
    float2*         P0     = (float2*)smem;
    float2*         P1     = (float2*)(smem + 32768);
    unsigned short* s_nbr  = (unsigned short*)(smem + 65536);   // 96K
    unsigned short* s_perm = (unsigned short*)(smem + 163840);  // 8K
    unsigned char*  s_ca   = (unsigned char*)(smem + 172032);   // 4K

    #pragma unroll
    for (int s = 0; s < PPT; s++) {
        int k = tid + s * NTHR;
        P0[k] = g_pos[k];
        s_ca[k] = g_cnt[k];
    }
    {
        const uint4* src = (const uint4*)g_nbr;   // 96KB = 6144 uint4
        uint4* dst = (uint4*)s_nbr;
        #pragma unroll
        for (int s = 0; s < 12; s++) dst[tid + s * NTHR] = src[tid + s * NTHR];
    }
    if (tid < 16) s_hist[tid] = 0u;
    __syncthreads();

    // counting sort by candidate count (13 bins)
    #pragma unroll
    for (int s = 0; s < PPT; s++)
        atomicAdd(&s_hist[s_ca[tid + s * NTHR]], 1u);
    __syncthreads();
    if (tid == 0) {
        unsigned run = 0u;
        #pragma unroll
        for (int b = 0; b <= CAPT; b++) { unsigned c = s_hist[b]; s_hist[b] = run; run += c; }
    }
    __syncthreads();
    #pragma unroll
    for (int s = 0; s < PPT; s++) {
        int p = tid + s * NTHR;
        unsigned pos = atomicAdd(&s_hist[s_ca[p]], 1u);
        s_perm[pos] = (unsigned short)p;
    }
    __syncthreads();

    int pp[PPT], myc[PPT];
    #pragma unroll
    for (int s = 0; s < PPT; s++) {
        pp[s] = s_perm[tid + s * NTHR];
        myc[s] = s_ca[pp[s]];
    }

    const float THR   = (float)(2.0 * 3.15e-6);     // 2*Rc
    const float THR2G = THR * THR * 1.0005f;
    const float MOVC  = (float)(2.1 * 3.15e-6);

    float2* C = P0;
    float2* N = P1;
    for (int t = 0; t < 30; t++) {
        int mycoll = 0;
        #pragma unroll
        for (int s = 0; s < PPT; s++) {
            int p = pp[s];
            float2 pc = C[p];
            float mx = 0.f, my = 0.f;
            int cnt = myc[s];
            for (int k = 0; k < cnt; k++) {
                int j = s_nbr[k * NP + p];
                float2 q = C[j];
                float dx = q.x - pc.x, dy = q.y - pc.y;   // p_j - p_i
                float r2 = fmaf(dx, dx, dy * dy);
                if (r2 <= THR2G) {
                    float rinv = __frsqrt_rn(r2);
                    float absd = r2 * rinv;
                    if (absd <= THR) {
                        float f = (MOVC - absd) * 0.5f * rinv;
                        mx += dx * f;
                        my += dy * f;
                        mycoll = 1;
                    }
                }
            }
            N[p] = make_float2(pc.x - mx, pc.y - my);   // write to OTHER buffer
        }
        int any = __syncthreads_or(mycoll);   // single barrier per iteration
        float2* tmp = C; C = N; N = tmp;
        if (!any) break;                      // uniform decision
    }

    #pragma unroll
    for (int s = 0; s < PPT; s++) {
        int p = tid + s * NTHR;
        out[p * 2 + 0] = C[p].x;
        out[p * 2 + 1] = C[p].y;
    }
    if (tid == 0) g_done = 0;                 // reset for next graph replay
}

// ---------------------------------------------------------------------------
extern "C" void kernel_launch(void* const* d_in, const int* in_sizes, int n_in,
                              void* d_out, int out_size) {
    const float* pre    = (const float*)d_in[0];
    const float* pim    = (const float*)d_in[1];
    const float* ore    = (const float*)d_in[2];
    const float* oim    = (const float*)d_in[3];
    const float* deltas = (const float*)d_in[4];
    const float* rnoise = (const float*)d_in[5];
    const float* tnre   = (const float*)d_in[6];
    const float* tnim   = (const float*)d_in[7];
    float* out = (float*)d_out;

    cudaFuncSetAttribute(fused_kernel, cudaFuncAttributeMaxDynamicSharedMemorySize, SMEM_BYTES);
    fused_kernel<<<NBLK, NTHR, SMEM_BYTES>>>(pre, pim, ore, oim, deltas, rnoise,
                                             tnre, tnim, out);
}

// round 14
// speedup vs baseline: 19.9419x; 1.0007x over previous
#include <cuda_runtime.h>
#include <math.h>

#define NP    4096
#define NC    45       // cells per side
#define NCELL 2025
#define CPAD  2048
#define CAPT  12       // per-particle collision candidate cap
#define NBLK  4
#define NTHR  1024
#define PPT   4        // NP / NTHR

#define PI_F     3.1415927410125732f
#define TWOPI_F  6.2831854820251465f

// global scratch (no allocation allowed)
static __device__ float2         g_pos[NP];        // translated positions
static __device__ unsigned short g_nbr[CAPT * NP]; // [k][i] collision candidates
static __device__ unsigned char  g_cnt[NP];
static __device__ int            g_done;           // zero-init; reset by sweep block

#define INV_CELL ((float)NC / 1.28e-3f)

// smem union (bytes):
//  pair view : s_p f2[NP] 32K | s_o f2[NP] 32K | s_hc u32[CPAD] 8K |
//              s_scan u32[CPAD] 8K | s_cell u16[NP] 8K | s_srt u16[NP] 8K = 96K
//  sweep view: P0 f2[NP] 32K | P1 f2[NP] 32K | s_nbr u16[CAPT*NP] 96K |
//              s_perm u16[NP] 8K | s_ca u8[NP] 4K = 172K
#define SMEM_BYTES 176128

__global__ void __launch_bounds__(NTHR, 1)
fused_kernel(const float* __restrict__ pre, const float* __restrict__ pim,
             const float* __restrict__ ore, const float* __restrict__ oim,
             const float* __restrict__ deltas, const float* __restrict__ rnoise,
             const float* __restrict__ tnre, const float* __restrict__ tnim,
             float* __restrict__ out) {
    extern __shared__ char smem[];
    // pair view
    float2*         s_p    = (float2*)smem;
    float2*         s_o    = (float2*)(smem + 32768);
    unsigned int*   s_hc   = (unsigned int*)(smem + 65536);
    unsigned int*   s_scan = (unsigned int*)(smem + 73728);
    unsigned short* s_cell = (unsigned short*)(smem + 81920);
    unsigned short* s_srt  = (unsigned short*)(smem + 90112);

    __shared__ float s_ws[64];
    __shared__ float s_cms[2];
    __shared__ int   s_last;
    __shared__ unsigned s_hist[16];

    int tid = threadIdx.x;
    int lane = tid & 31, wrp = tid >> 5;    // 32 warps

    // ---- pair phase A: load + histogram + cms ----
    s_hc[tid] = 0u; s_hc[tid + NTHR] = 0u;
    __syncthreads();

    float ax = 0.f, ay = 0.f;
    #pragma unroll
    for (int s = 0; s < PPT; s++) {
        int k = tid + s * NTHR;
        float px = pre[k], py = pim[k];
        s_p[k] = make_float2(px, py);
        s_o[k] = make_float2(ore[k], oim[k]);
        int cx = (int)(px * INV_CELL); cx = cx < 0 ? 0 : (cx > NC - 1 ? NC - 1 : cx);
        int cy = (int)(py * INV_CELL); cy = cy < 0 ? 0 : (cy > NC - 1 ? NC - 1 : cy);
        int cell = cy * NC + cx;
        s_cell[k] = (unsigned short)cell;
        atomicAdd(&s_hc[cell], 1u);
        ax += px; ay += py;
    }
    #pragma unroll
    for (int o = 16; o > 0; o >>= 1) {
        ax += __shfl_down_sync(0xffffffffu, ax, o);
        ay += __shfl_down_sync(0xffffffffu, ay, o);
    }
    if (lane == 0) { s_ws[wrp] = ax; s_ws[32 + wrp] = ay; }
    __syncthreads();
    if (tid == 0) {
        float sx = 0.f, sy = 0.f;
        #pragma unroll
        for (int w = 0; w < 32; w++) { sx += s_ws[w]; sy += s_ws[32 + w]; }
        s_cms[0] = sx * (1.0f / NP);        // n_a = 4096 exactly
        s_cms[1] = sy * (1.0f / NP);
    }
    __syncthreads();

    // ---- inclusive scan over 2048 cells: 2 cells/thread + warp shfl ----
    {
        unsigned v0, v1;
        int base = tid * 2;
        v0 = s_hc[base];
        v1 = v0 + s_hc[base + 1];
        unsigned tot = v1;
        #pragma unroll
        for (int o = 1; o < 32; o <<= 1) {
            unsigned n = __shfl_up_sync(0xffffffffu, tot, o);
            if (lane >= o) tot += n;
        }
        if (lane == 31) ((unsigned*)s_ws)[wrp] = tot;
        unsigned lanepre = tot - v1;
        __syncthreads();
        unsigned wpre = 0u;
        #pragma unroll
        for (int w = 0; w < 32; w++) { unsigned t = ((unsigned*)s_ws)[w]; if (w < wrp) wpre += t; }
        unsigned off = wpre + lanepre;
        s_scan[base] = v0 + off;
        s_scan[base + 1] = v1 + off;
    }
    __syncthreads();
    {
        int c0 = tid, c1 = tid + NTHR;
        s_hc[c0] = s_scan[c0] - s_hc[c0];   // cursor = exclusive start
        s_hc[c1] = s_scan[c1] - s_hc[c1];
    }
    __syncthreads();
    #pragma unroll
    for (int s = 0; s < PPT; s++) {
        int k = tid + s * NTHR;
        unsigned pos = atomicAdd(&s_hc[s_cell[k]], 1u);
        s_srt[pos] = (unsigned short)k;
    }
    __syncthreads();

    // ---- pair phase B: neighborhood scan for this block's 1024 particles ----
    const float ROCf  = (float)(2.5e-5 + 3.15e-6);   // RO + RC = 28.15um
    const float ROC2G = ROCf * ROCf * 1.0005f;
    const float RRf   = (float)(8e-6);
    const float RCAP  = (float)(4.5 * 3.15e-6);
    const float RCAP2 = RCAP * RCAP;

    int i = blockIdx.x * NTHR + tid;
    float pxi = s_p[i].x, pyi = s_p[i].y;
    float orr = s_o[i].x, ori = s_o[i].y;

    int cell = s_cell[i];
    int cx = cell % NC, cy = cell / NC;
    int x0 = cx > 0 ? cx - 1 : 0, x1 = cx < NC - 1 ? cx + 1 : NC - 1;
    int y0 = cy > 0 ? cy - 1 : 0, y1 = cy < NC - 1 ? cy + 1 : NC - 1;

    float nr = 0.f, sxv = 0.f, syv = 0.f, oxv = 0.f, oyv = 0.f;
    int cc = 0;

    for (int gy = y0; gy <= y1; gy++) {
        int c0 = gy * NC + x0;
        int c1 = gy * NC + x1;
        int b = (c0 == 0) ? 0 : (int)s_scan[c0 - 1];
        int e = (int)s_scan[c1];
        for (int k = b; k < e; k++) {
            int j = s_srt[k];
            float2 pj = s_p[j];
            float dx = pxi - pj.x, dy = pyi - pj.y;
            float r2 = fmaf(dx, dx, dy * dy);
            bool same = (j == i);
            if (r2 <= ROC2G || same) {
                if (r2 <= RCAP2 && !same) {                 // collision candidate
                    if (cc < CAPT) g_nbr[cc * NP + i] = (unsigned short)j;
                    cc++;
                }
                float dist = same ? 1.0f : __fsqrt_rn(r2);  // diag dist = 1 (eye)
                float2 oj = s_o[j];
                if (dist <= ROCf || same) {                 // mask_ro (self incl.)
                    oxv += oj.x;
                    oyv += oj.y;
                }
                if (dist <= RRf && !same) {                 // mask_rr (self excl.)
                    // in_front: |wrap(ang_i - ang_j)| < pi/2 <=> ori_i . ori_j > 0
                    if (fmaf(orr, oj.x, ori * oj.y) > 0.f) {
                        nr += 1.0f; sxv += pj.x; syv += pj.y;
                    }
                }
            }
        }
    }
    g_cnt[i] = (unsigned char)(cc > CAPT ? CAPT : cc);

    // ---- epilogue ----
    float sgn = (nr > 0.f) ? 1.f : 0.f;
    float den = fmaxf(nr, 1.f);
    float SSx = sxv / den - pxi * sgn;
    float SSy = syv / den - pyi * sgn;
    float ddx = -SSx, ddy = -SSy;

    float Px = s_cms[0] - pxi;               // Ps = cms - pos (Ra = inf)
    float Py = s_cms[1] - pyi;

    float del = deltas[i];
    float cd = cosf(del), sd = sinf(del);
    float lx = Px * cd - Py * sd;
    float ly = Px * sd + Py * cd;
    float rxx = Px * cd + Py * sd;
    float ryy = Py * cd - Px * sd;

    float dl = lx * oxv + ly * oyv;
    float dr = rxx * oxv + ryy * oyv;
    float no = fmaxf(__fsqrt_rn(oxv * oxv + oyv * oyv), 1e-14f);
    float cl = dl / (fmaxf(__fsqrt_rn(lx * lx + ly * ly), 1e-14f) * no);
    float cr = dr / (fmaxf(__fsqrt_rn(rxx * rxx + ryy * ryy), 1e-14f) * no);
    bool usel = (cl >= cr);
    float bx = usel ? lx : rxx;
    float by = usel ? ly : ryy;

    bool hasrep = (ddx != 0.f) || (ddy != 0.f);
    float tx = hasrep ? ddx : bx;
    float ty = hasrep ? ddy : by;
    float att = atan2f(ty, tx) - atan2f(ori, orr);
    if (att <= -PI_F) { float r = fmodf(att, PI_F); if (r < 0.f) r += PI_F; att = r; }
    if (att >= PI_F) att -= TWOPI_F;

    const float CTH  = (float)(0.2 * 25.0 * 0.0028);
    const float S2DR = (float)0.07483314773547883;
    const float SDT  = (float)0.4472135954999579;
    float theta = CTH * sinf(att) + rnoise[i] * S2DR * SDT;
    float rc = cosf(theta), rs = sinf(theta);
    float nore = orr * rc - ori * rs;
    float noim = orr * rs + ori * rc;

    const float CH    = (float)0.7071067811865476;
    const float CTT   = (float)1.6733200530681511e-7;
    const float DTVEL = (float)(0.2 * 5e-7);
    float tnr = tnre[i] * CH * CTT;
    float tni = tnim[i] * CH * CTT;
    g_pos[i] = make_float2(pxi + (DTVEL * orr + tnr * SDT),
                           pyi + (DTVEL * ori + tni * SDT));

    out[(1 * NP + i) * 2 + 0] = nore;
    out[(1 * NP + i) * 2 + 1] = noim;
    out[(2 * NP + i) * 2 + 0] = oxv;
    out[(2 * NP + i) * 2 + 1] = oyv;
    out[(3 * NP + i) * 2 + 0] = lx;
    out[(3 * NP + i) * 2 + 1] = ly;
    out[(4 * NP + i) * 2 + 0] = rxx;
    out[(4 * NP + i) * 2 + 1] = ryy;

    // ---- last-block ticket ----
    __syncthreads();
    if (tid == 0) {
        __threadfence();
        int v = atomicAdd(&g_done, 1);
        s_last = (v == NBLK - 1) ? 1 : 0;
    }
    __syncthreads();
    if (!s_last) return;
    __threadfence();   // acquire all blocks' g_pos / g_nbr / g_cnt writes

    // ---- sweep phase (last block), cnt-sorted assignment ----
    float2*         P0     = (float2*)smem;
    float2*         P1     = (float2*)(smem + 32768);
    unsigned short* s_nbr  = (unsigned short*)(smem + 65536);   // 96K
    unsigned short* s_perm = (unsigned short*)(smem + 163840);  // 8K
    unsigned char*  s_ca   = (unsigned char*)(smem + 172032);   // 4K

    #pragma unroll
    for (int s = 0; s < PPT; s++) {
        int k = tid + s * NTHR;
        P0[k] = g_pos[k];
        s_ca[k] = g_cnt[k];
    }
    {
        const uint4* src = (const uint4*)g_nbr;   // 96KB = 6144 uint4
        uint4* dst = (uint4*)s_nbr;
        #pragma unroll
        for (int s = 0; s < 6; s++) dst[tid + s * NTHR] = src[tid + s * NTHR];
    }
    if (tid < 16) s_hist[tid] = 0u;
    __syncthreads();

    // counting sort by candidate count (13 bins)
    #pragma unroll
    for (int s = 0; s < PPT; s++)
        atomicAdd(&s_hist[s_ca[tid + s * NTHR]], 1u);
    __syncthreads();
    if (tid == 0) {
        unsigned run = 0u;
        #pragma unroll
        for (int b = 0; b <= CAPT; b++) { unsigned c = s_hist[b]; s_hist[b] = run; run += c; }
    }
    __syncthreads();
    #pragma unroll
    for (int s = 0; s < PPT; s++) {
        int p = tid + s * NTHR;
        unsigned pos = atomicAdd(&s_hist[s_ca[p]], 1u);
        s_perm[pos] = (unsigned short)p;
    }
    __syncthreads();

    int pp[PPT], myc[PPT];
    #pragma unroll
    for (int s = 0; s < PPT; s++) {
        pp[s] = s_perm[tid + s * NTHR];
        myc[s] = s_ca[pp[s]];
    }

    const float THR   = (float)(2.0 * 3.15e-6);     // 2*Rc
    const float THR2G = THR * THR * 1.0005f;
    const float MOVC  = (float)(2.1 * 3.15e-6);

    float2* C = P0;
    float2* N = P1;
    for (int t = 0; t < 30; t++) {
        int mycoll = 0;
        #pragma unroll
        for (int s = 0; s < PPT; s++) {
            int p = pp[s];
            float2 pc = C[p];
            float mx = 0.f, my = 0.f;
            int cnt = myc[s];
            for (int k = 0; k < cnt; k++) {
                int j = s_nbr[k * NP + p];
                float2 q = C[j];
                float dx = q.x - pc.x, dy = q.y - pc.y;   // p_j - p_i
                float r2 = fmaf(dx, dx, dy * dy);
                if (r2 <= THR2G) {
                    float rinv = __frsqrt_rn(r2);
                    float absd = r2 * rinv;
                    if (absd <= THR) {
                        float f = (MOVC - absd) * 0.5f * rinv;
                        mx += dx * f;
                        my += dy * f;
                        mycoll = 1;
                    }
                }
            }
            N[p] = make_float2(pc.x - mx, pc.y - my);   // write to OTHER buffer
        }
        int any = __syncthreads_or(mycoll);   // single barrier per iteration
        float2* tmp = C; C = N; N = tmp;
        if (!any) break;                      // uniform decision
    }

    #pragma unroll
    for (int s = 0; s < PPT; s++) {
        int p = tid + s * NTHR;
        out[p * 2 + 0] = C[p].x;
        out[p * 2 + 1] = C[p].y;
    }
    if (tid == 0) g_done = 0;                 // reset for next graph replay
}

// ---------------------------------------------------------------------------
extern "C" void kernel_launch(void* const* d_in, const int* in_sizes, int n_in,
                              void* d_out, int out_size) {
    const float* pre    = (const float*)d_in[0];
    const float* pim    = (const float*)d_in[1];
    const float* ore    = (const float*)d_in[2];
    const float* oim    = (const float*)d_in[3];
    const float* deltas = (const float*)d_in[4];
    const float* rnoise = (const float*)d_in[5];
    const float* tnre   = (const float*)d_in[6];
    const float* tnim   = (const float*)d_in[7];
    float* out = (float*)d_out;

    cudaFuncSetAttribute(fused_kernel, cudaFuncAttributeMaxDynamicSharedMemorySize, SMEM_BYTES);
    fused_kernel<<<NBLK, NTHR, SMEM_BYTES>>>(pre, pim, ore, oim, deltas, rnoise,
                                             tnre, tnim, out);
}